// round 1
// baseline (speedup 1.0000x reference)
#include <cuda_runtime.h>
#include <cuda_bf16.h>
#include <math.h>

// ---------------------------------------------------------------------------
// Problem constants
// ---------------------------------------------------------------------------
#define BATCH   16
#define SEQ     577
#define TOK     (BATCH * SEQ)        // 9232
#define DIM     1024
#define HEADS   16
#define HDIM    64                   // DIM / HEADS
#define HIDDEN  4096
#define EPS     1e-5f
#define SCALE   0.125f               // 1/sqrt(64)

// ---------------------------------------------------------------------------
// Scratch (device globals; allocation inside kernel_launch is forbidden)
// ---------------------------------------------------------------------------
__device__ float g_xn [TOK * DIM];      // LN output (reused for LN1 and LN2)
__device__ float g_qkv[TOK * 3 * DIM];  // QKV projection
__device__ float g_y  [TOK * DIM];      // attention output (token-major, h*64+d)
__device__ float g_x1 [TOK * DIM];      // x after attention residual
__device__ float g_h  [TOK * HIDDEN];   // GELU(fc1) output

// ---------------------------------------------------------------------------
// LayerNorm: one block per token, 256 threads, 4 floats/thread, two-pass
// ---------------------------------------------------------------------------
__device__ __forceinline__ float block_reduce_sum(float v, float* red) {
    int lane = threadIdx.x & 31, wid = threadIdx.x >> 5;
    #pragma unroll
    for (int o = 16; o > 0; o >>= 1) v += __shfl_xor_sync(0xffffffffu, v, o);
    if (lane == 0) red[wid] = v;
    __syncthreads();
    v = (lane < 8) ? red[lane] : 0.f;
    #pragma unroll
    for (int o = 4; o > 0; o >>= 1) v += __shfl_xor_sync(0xffffffffu, v, o);
    v = __shfl_sync(0xffffffffu, v, 0);
    return v;
}

__global__ __launch_bounds__(256) void ln_kernel(
    const float* __restrict__ x, const float* __restrict__ g,
    const float* __restrict__ b, float* __restrict__ out)
{
    __shared__ float red[8];
    size_t row = blockIdx.x;
    const float4* xr = (const float4*)(x + row * DIM);
    int t = threadIdx.x;
    float4 v = xr[t];
    float s = v.x + v.y + v.z + v.w;
    float mean = block_reduce_sum(s, red) * (1.f / DIM);
    __syncthreads();
    float dx0 = v.x - mean, dx1 = v.y - mean, dx2 = v.z - mean, dx3 = v.w - mean;
    float s2 = dx0*dx0 + dx1*dx1 + dx2*dx2 + dx3*dx3;
    float var = block_reduce_sum(s2, red) * (1.f / DIM);
    float rs = rsqrtf(var + EPS);
    float4 gg = ((const float4*)g)[t];
    float4 bb = ((const float4*)b)[t];
    float4 o;
    o.x = dx0 * rs * gg.x + bb.x;
    o.y = dx1 * rs * gg.y + bb.y;
    o.z = dx2 * rs * gg.z + bb.z;
    o.w = dx3 * rs * gg.w + bb.w;
    ((float4*)(out + row * DIM))[t] = o;
}

// ---------------------------------------------------------------------------
// SGEMM-NT: C[M,Nc] = A[M,K] @ B[Nc,K]^T (+bias +gelu +residual)
// 128x128 tile, BK=8, 256 threads, 8x8 micro-tile per thread.
// Nc and K are multiples of 128 / 8; only M needs guarding.
// ---------------------------------------------------------------------------
#define EPI_BIAS 1
#define EPI_GELU 2
#define EPI_RES  4

template<int FLAGS>
__global__ __launch_bounds__(256) void sgemm_nt(
    const float* __restrict__ A, const float* __restrict__ Bw,
    const float* __restrict__ bias, const float* __restrict__ res,
    float* __restrict__ C, int M, int Nc, int K)
{
    constexpr int BM = 128, BN = 128, BK = 8;
    __shared__ float As[BK][BM + 4];
    __shared__ float Bs[BK][BN + 4];

    int tid = threadIdx.x;
    int m0 = blockIdx.y * BM, n0 = blockIdx.x * BN;

    int l_r = tid >> 1;            // 0..127
    int l_c = (tid & 1) << 2;      // 0 or 4

    int ty = tid >> 4, tx = tid & 15;
    int mm = ty * 8, nn = tx * 8;

    float acc[8][8];
    #pragma unroll
    for (int i = 0; i < 8; i++)
        #pragma unroll
        for (int j = 0; j < 8; j++) acc[i][j] = 0.f;

    const int ga_r = m0 + l_r;
    const bool a_ok = (ga_r < M);
    const float* Aptr = A + (size_t)(a_ok ? ga_r : 0) * K + l_c;
    const float* Bptr = Bw + (size_t)(n0 + l_r) * K + l_c;

    for (int k0 = 0; k0 < K; k0 += BK) {
        float4 av = make_float4(0.f, 0.f, 0.f, 0.f);
        if (a_ok) av = *(const float4*)(Aptr + k0);
        float4 bv = *(const float4*)(Bptr + k0);
        As[l_c + 0][l_r] = av.x; As[l_c + 1][l_r] = av.y;
        As[l_c + 2][l_r] = av.z; As[l_c + 3][l_r] = av.w;
        Bs[l_c + 0][l_r] = bv.x; Bs[l_c + 1][l_r] = bv.y;
        Bs[l_c + 2][l_r] = bv.z; Bs[l_c + 3][l_r] = bv.w;
        __syncthreads();

        #pragma unroll
        for (int kk = 0; kk < BK; kk++) {
            float4 a0 = *(const float4*)&As[kk][mm];
            float4 a1 = *(const float4*)&As[kk][mm + 4];
            float4 b0 = *(const float4*)&Bs[kk][nn];
            float4 b1 = *(const float4*)&Bs[kk][nn + 4];
            float af[8] = {a0.x,a0.y,a0.z,a0.w,a1.x,a1.y,a1.z,a1.w};
            float bf[8] = {b0.x,b0.y,b0.z,b0.w,b1.x,b1.y,b1.z,b1.w};
            #pragma unroll
            for (int i = 0; i < 8; i++)
                #pragma unroll
                for (int j = 0; j < 8; j++)
                    acc[i][j] = fmaf(af[i], bf[j], acc[i][j]);
        }
        __syncthreads();
    }

    #pragma unroll
    for (int i = 0; i < 8; i++) {
        int r = m0 + mm + i;
        if (r >= M) break;
        size_t base = (size_t)r * Nc + n0 + nn;
        #pragma unroll
        for (int j = 0; j < 8; j++) {
            float v = acc[i][j];
            if (FLAGS & EPI_BIAS) v += bias[n0 + nn + j];
            if (FLAGS & EPI_GELU) v = 0.5f * v * (1.f + erff(v * 0.70710678118654752f));
            if (FLAGS & EPI_RES)  v += res[base + j];
            C[base + j] = v;
        }
    }
}

// ---------------------------------------------------------------------------
// Attention: grid (ceil(577/16), B*H). Block: 256 threads, 16 query rows.
// K/V streamed through smem in 64-key chunks; full 16x577 score tile in smem.
// ---------------------------------------------------------------------------
#define AT_TQ 16
#define AT_CK 64
#define SCP   592   // padded score row stride (>=577, mult of 16)
#define ATTN_SMEM ((AT_TQ*65 + AT_CK*65 + AT_TQ*SCP) * (int)sizeof(float))

__global__ __launch_bounds__(256) void attn_kernel(
    const float* __restrict__ qkv, float* __restrict__ out)
{
    extern __shared__ float sm[];
    float* qs = sm;                    // [16][65]
    float* ks = qs + AT_TQ * 65;       // [64][65]  (K chunk, then reused for V)
    float* sc = ks + AT_CK * 65;       // [16][SCP]

    int bh = blockIdx.y;
    int b = bh >> 4, h = bh & 15;
    int q0 = blockIdx.x * AT_TQ;
    int t = threadIdx.x;

    // load Q tile
    for (int i = t; i < AT_TQ * HDIM; i += 256) {
        int r = i >> 6, d = i & 63;
        int qi = q0 + r;
        qs[r * 65 + d] = (qi < SEQ)
            ? qkv[((size_t)(b * SEQ + qi)) * (3 * DIM) + h * HDIM + d] : 0.f;
    }

    int rb = (t >> 5) * 2;   // query-row pair base: 0..14
    int cb = (t & 31) * 2;   // key/dim pair base:   0..62

    const int nchunk = (SEQ + AT_CK - 1) / AT_CK;  // 10

    // ---- scores ----
    for (int kc = 0; kc < nchunk; kc++) {
        int jcnt = min(AT_CK, SEQ - kc * AT_CK);
        __syncthreads();
        for (int i = t; i < AT_CK * HDIM; i += 256) {
            int j = i >> 6, d = i & 63;
            int jg = kc * AT_CK + j;
            ks[j * 65 + d] = (jg < SEQ)
                ? qkv[((size_t)(b * SEQ + jg)) * (3 * DIM) + DIM + h * HDIM + d] : 0.f;
        }
        __syncthreads();
        float s00 = 0.f, s01 = 0.f, s10 = 0.f, s11 = 0.f;
        #pragma unroll 16
        for (int d = 0; d < HDIM; d++) {
            float qa = qs[rb * 65 + d], qb = qs[(rb + 1) * 65 + d];
            float ka = ks[cb * 65 + d], kb = ks[(cb + 1) * 65 + d];
            s00 = fmaf(qa, ka, s00); s01 = fmaf(qa, kb, s01);
            s10 = fmaf(qb, ka, s10); s11 = fmaf(qb, kb, s11);
        }
        int jg0 = kc * AT_CK + cb;
        if (cb < jcnt) {
            sc[rb * SCP + jg0]       = s00 * SCALE;
            sc[(rb + 1) * SCP + jg0] = s10 * SCALE;
        }
        if (cb + 1 < jcnt) {
            sc[rb * SCP + jg0 + 1]       = s01 * SCALE;
            sc[(rb + 1) * SCP + jg0 + 1] = s11 * SCALE;
        }
    }
    __syncthreads();

    // ---- softmax (16 threads per row, rows r = t>>4) ----
    {
        int r = t >> 4, l = t & 15;
        float m = -1e30f;
        for (int j = l; j < SEQ; j += 16) m = fmaxf(m, sc[r * SCP + j]);
        #pragma unroll
        for (int o = 8; o > 0; o >>= 1) m = fmaxf(m, __shfl_xor_sync(0xffffffffu, m, o, 16));
        float ssum = 0.f;
        for (int j = l; j < SEQ; j += 16) {
            float e = __expf(sc[r * SCP + j] - m);
            sc[r * SCP + j] = e;
            ssum += e;
        }
        #pragma unroll
        for (int o = 8; o > 0; o >>= 1) ssum += __shfl_xor_sync(0xffffffffu, ssum, o, 16);
        float inv = 1.f / ssum;
        for (int j = l; j < SCP; j += 16)
            sc[r * SCP + j] = (j < SEQ) ? sc[r * SCP + j] * inv : 0.f;
    }

    // ---- AV ----
    float a00 = 0.f, a01 = 0.f, a10 = 0.f, a11 = 0.f;
    for (int kc = 0; kc < nchunk; kc++) {
        int jcnt = min(AT_CK, SEQ - kc * AT_CK);
        __syncthreads();
        for (int i = t; i < AT_CK * HDIM; i += 256) {
            int j = i >> 6, d = i & 63;
            int jg = kc * AT_CK + j;
            ks[j * 65 + d] = (jg < SEQ)
                ? qkv[((size_t)(b * SEQ + jg)) * (3 * DIM) + 2 * DIM + h * HDIM + d] : 0.f;
        }
        __syncthreads();
        int jbase = kc * AT_CK;
        for (int jj = 0; jj < jcnt; jj++) {
            float p0 = sc[rb * SCP + jbase + jj];
            float p1 = sc[(rb + 1) * SCP + jbase + jj];
            float v0 = ks[jj * 65 + cb];
            float v1 = ks[jj * 65 + cb + 1];
            a00 = fmaf(p0, v0, a00); a01 = fmaf(p0, v1, a01);
            a10 = fmaf(p1, v0, a10); a11 = fmaf(p1, v1, a11);
        }
    }

    int qi0 = q0 + rb;
    if (qi0 < SEQ) {
        size_t o = (size_t)(b * SEQ + qi0) * DIM + h * HDIM + cb;
        out[o] = a00; out[o + 1] = a01;
    }
    if (qi0 + 1 < SEQ) {
        size_t o = (size_t)(b * SEQ + qi0 + 1) * DIM + h * HDIM + cb;
        out[o] = a10; out[o + 1] = a11;
    }
}

// ---------------------------------------------------------------------------
// Launch
// ---------------------------------------------------------------------------
extern "C" void kernel_launch(void* const* d_in, const int* in_sizes, int n_in,
                              void* d_out, int out_size)
{
    const float* x      = (const float*)d_in[0];
    const float* w_qkv  = (const float*)d_in[1];
    const float* b_qkv  = (const float*)d_in[2];
    const float* w_proj = (const float*)d_in[3];
    const float* b_proj = (const float*)d_in[4];
    const float* ln1_g  = (const float*)d_in[5];
    const float* ln1_b  = (const float*)d_in[6];
    const float* ln2_g  = (const float*)d_in[7];
    const float* ln2_b  = (const float*)d_in[8];
    const float* w_fc1  = (const float*)d_in[9];
    const float* b_fc1  = (const float*)d_in[10];
    const float* w_fc2  = (const float*)d_in[11];
    const float* b_fc2  = (const float*)d_in[12];
    float* out = (float*)d_out;

    float *p_xn, *p_qkv, *p_y, *p_x1, *p_h;
    cudaGetSymbolAddress((void**)&p_xn,  g_xn);
    cudaGetSymbolAddress((void**)&p_qkv, g_qkv);
    cudaGetSymbolAddress((void**)&p_y,   g_y);
    cudaGetSymbolAddress((void**)&p_x1,  g_x1);
    cudaGetSymbolAddress((void**)&p_h,   g_h);

    cudaFuncSetAttribute(attn_kernel,
        cudaFuncAttributeMaxDynamicSharedMemorySize, ATTN_SMEM);

    const int MB = (TOK + 127) / 128;   // 73

    // 1. LN1
    ln_kernel<<<TOK, 256>>>(x, ln1_g, ln1_b, p_xn);
    // 2. QKV = xn @ w_qkv^T + b_qkv
    sgemm_nt<EPI_BIAS><<<dim3(3 * DIM / 128, MB), 256>>>(
        p_xn, w_qkv, b_qkv, nullptr, p_qkv, TOK, 3 * DIM, DIM);
    // 3. attention
    attn_kernel<<<dim3((SEQ + AT_TQ - 1) / AT_TQ, BATCH * HEADS), 256, ATTN_SMEM>>>(
        p_qkv, p_y);
    // 4. x1 = y @ w_proj^T + b_proj + x
    sgemm_nt<EPI_BIAS | EPI_RES><<<dim3(DIM / 128, MB), 256>>>(
        p_y, w_proj, b_proj, x, p_x1, TOK, DIM, DIM);
    // 5. LN2
    ln_kernel<<<TOK, 256>>>(p_x1, ln2_g, ln2_b, p_xn);
    // 6. h = gelu(xn @ w_fc1^T + b_fc1)
    sgemm_nt<EPI_BIAS | EPI_GELU><<<dim3(HIDDEN / 128, MB), 256>>>(
        p_xn, w_fc1, b_fc1, nullptr, p_h, TOK, HIDDEN, DIM);
    // 7. out = h @ w_fc2^T + b_fc2 + x1
    sgemm_nt<EPI_BIAS | EPI_RES><<<dim3(DIM / 128, MB), 256>>>(
        p_h, w_fc2, b_fc2, p_x1, out, TOK, DIM, HIDDEN);
}

// round 2
// speedup vs baseline: 1.7322x; 1.7322x over previous
#include <cuda_runtime.h>
#include <cuda_bf16.h>
#include <math.h>

// ---------------------------------------------------------------------------
// Problem constants
// ---------------------------------------------------------------------------
#define BATCH   16
#define SEQ     577
#define TOK     (BATCH * SEQ)        // 9232
#define DIM     1024
#define HEADS   16
#define HDIM    64
#define HIDDEN  4096
#define EPS     1e-5f
#define SCALE   0.125f

// ---------------------------------------------------------------------------
// Scratch
// ---------------------------------------------------------------------------
__device__ float g_xn [TOK * DIM];
__device__ float g_qkv[TOK * 3 * DIM];
__device__ float g_y  [TOK * DIM];
__device__ float g_x1 [TOK * DIM];
__device__ float g_h  [TOK * HIDDEN];

// ---------------------------------------------------------------------------
// LayerNorm
// ---------------------------------------------------------------------------
__device__ __forceinline__ float block_reduce_sum(float v, float* red) {
    int lane = threadIdx.x & 31, wid = threadIdx.x >> 5;
    #pragma unroll
    for (int o = 16; o > 0; o >>= 1) v += __shfl_xor_sync(0xffffffffu, v, o);
    if (lane == 0) red[wid] = v;
    __syncthreads();
    v = (lane < 8) ? red[lane] : 0.f;
    #pragma unroll
    for (int o = 4; o > 0; o >>= 1) v += __shfl_xor_sync(0xffffffffu, v, o);
    v = __shfl_sync(0xffffffffu, v, 0);
    return v;
}

__global__ __launch_bounds__(256) void ln_kernel(
    const float* __restrict__ x, const float* __restrict__ g,
    const float* __restrict__ b, float* __restrict__ out)
{
    __shared__ float red[8];
    size_t row = blockIdx.x;
    const float4* xr = (const float4*)(x + row * DIM);
    int t = threadIdx.x;
    float4 v = xr[t];
    float s = v.x + v.y + v.z + v.w;
    float mean = block_reduce_sum(s, red) * (1.f / DIM);
    __syncthreads();
    float dx0 = v.x - mean, dx1 = v.y - mean, dx2 = v.z - mean, dx3 = v.w - mean;
    float s2 = dx0*dx0 + dx1*dx1 + dx2*dx2 + dx3*dx3;
    float var = block_reduce_sum(s2, red) * (1.f / DIM);
    float rs = rsqrtf(var + EPS);
    float4 gg = ((const float4*)g)[t];
    float4 bb = ((const float4*)b)[t];
    float4 o;
    o.x = dx0 * rs * gg.x + bb.x;
    o.y = dx1 * rs * gg.y + bb.y;
    o.z = dx2 * rs * gg.z + bb.z;
    o.w = dx3 * rs * gg.w + bb.w;
    ((float4*)(out + row * DIM))[t] = o;
}

// ---------------------------------------------------------------------------
// TF32 tensor-core GEMM-NT: C[M,Nc] = A[M,K] @ B[Nc,K]^T (+bias/gelu/res)
// 128x128x16 tile, 256 threads (8 warps), each warp 32x64 via m16n8k8 mma.
// ---------------------------------------------------------------------------
#define EPI_BIAS 1
#define EPI_GELU 2
#define EPI_RES  4

__device__ __forceinline__ unsigned f2tf32(float f) {
    unsigned u;
    asm("cvt.rna.tf32.f32 %0, %1;" : "=r"(u) : "f"(f));
    return u;
}

__device__ __forceinline__ void mma_tf32(
    float c[4], unsigned a0, unsigned a1, unsigned a2, unsigned a3,
    unsigned b0, unsigned b1)
{
    asm volatile(
        "mma.sync.aligned.m16n8k8.row.col.f32.tf32.tf32.f32 "
        "{%0,%1,%2,%3}, {%4,%5,%6,%7}, {%8,%9}, {%0,%1,%2,%3};\n"
        : "+f"(c[0]), "+f"(c[1]), "+f"(c[2]), "+f"(c[3])
        : "r"(a0), "r"(a1), "r"(a2), "r"(a3), "r"(b0), "r"(b1));
}

#define LDP 136   // smem row stride (floats): 8-bank shift per k-row -> conflict-free

template<int FLAGS>
__global__ __launch_bounds__(256) void gemm_tf32(
    const float* __restrict__ A, const float* __restrict__ Bw,
    const float* __restrict__ bias, const float* __restrict__ res,
    float* __restrict__ C, int M, int Nc, int K)
{
    constexpr int BM = 128, BN = 128, BK = 16;
    __shared__ unsigned As[BK][LDP];
    __shared__ unsigned Bs[BK][LDP];

    int tid = threadIdx.x;
    int m0 = blockIdx.y * BM, n0 = blockIdx.x * BN;

    // loader coords: each thread loads 8 consecutive K-floats of one row
    int l_r = tid >> 1;
    int l_c = (tid & 1) << 3;

    int warp = tid >> 5, lane = tid & 31;
    int wm = warp & 3;        // 4 m-strips of 32
    int wn = warp >> 2;       // 2 n-strips of 64
    int g  = lane >> 2;       // 0..7
    int tg = lane & 3;        // 0..3

    float acc[2][8][4];
    #pragma unroll
    for (int i = 0; i < 2; i++)
        #pragma unroll
        for (int j = 0; j < 8; j++)
            #pragma unroll
            for (int c = 0; c < 4; c++) acc[i][j][c] = 0.f;

    const int arow = m0 + l_r;
    const bool a_ok = (arow < M);
    const float* Ap = A + (size_t)(a_ok ? arow : 0) * K + l_c;
    const float* Bp = Bw + (size_t)(n0 + l_r) * K + l_c;

    for (int k0 = 0; k0 < K; k0 += BK) {
        float4 av0 = make_float4(0.f,0.f,0.f,0.f), av1 = av0;
        if (a_ok) {
            av0 = *(const float4*)(Ap + k0);
            av1 = *(const float4*)(Ap + k0 + 4);
        }
        float4 bv0 = *(const float4*)(Bp + k0);
        float4 bv1 = *(const float4*)(Bp + k0 + 4);

        As[l_c + 0][l_r] = f2tf32(av0.x); As[l_c + 1][l_r] = f2tf32(av0.y);
        As[l_c + 2][l_r] = f2tf32(av0.z); As[l_c + 3][l_r] = f2tf32(av0.w);
        As[l_c + 4][l_r] = f2tf32(av1.x); As[l_c + 5][l_r] = f2tf32(av1.y);
        As[l_c + 6][l_r] = f2tf32(av1.z); As[l_c + 7][l_r] = f2tf32(av1.w);
        Bs[l_c + 0][l_r] = f2tf32(bv0.x); Bs[l_c + 1][l_r] = f2tf32(bv0.y);
        Bs[l_c + 2][l_r] = f2tf32(bv0.z); Bs[l_c + 3][l_r] = f2tf32(bv0.w);
        Bs[l_c + 4][l_r] = f2tf32(bv1.x); Bs[l_c + 5][l_r] = f2tf32(bv1.y);
        Bs[l_c + 6][l_r] = f2tf32(bv1.z); Bs[l_c + 7][l_r] = f2tf32(bv1.w);
        __syncthreads();

        #pragma unroll
        for (int ks = 0; ks < 2; ks++) {
            int kk = ks * 8;
            unsigned a[2][4];
            int mb = wm * 32;
            #pragma unroll
            for (int i = 0; i < 2; i++) {
                int mr = mb + i * 16 + g;
                a[i][0] = As[kk + tg    ][mr];
                a[i][1] = As[kk + tg    ][mr + 8];
                a[i][2] = As[kk + tg + 4][mr];
                a[i][3] = As[kk + tg + 4][mr + 8];
            }
            int nb = wn * 64;
            #pragma unroll
            for (int j = 0; j < 8; j++) {
                unsigned b0 = Bs[kk + tg    ][nb + j * 8 + g];
                unsigned b1 = Bs[kk + tg + 4][nb + j * 8 + g];
                mma_tf32(acc[0][j], a[0][0], a[0][1], a[0][2], a[0][3], b0, b1);
                mma_tf32(acc[1][j], a[1][0], a[1][1], a[1][2], a[1][3], b0, b1);
            }
        }
        __syncthreads();
    }

    // epilogue
    #pragma unroll
    for (int i = 0; i < 2; i++) {
        #pragma unroll
        for (int j = 0; j < 8; j++) {
            int row0 = m0 + wm * 32 + i * 16 + g;
            int row1 = row0 + 8;
            int col  = n0 + wn * 64 + j * 8 + tg * 2;
            float bia0 = 0.f, bia1 = 0.f;
            if (FLAGS & EPI_BIAS) { bia0 = bias[col]; bia1 = bias[col + 1]; }
            #pragma unroll
            for (int half = 0; half < 2; half++) {
                int r = half ? row1 : row0;
                if (r < M) {
                    float v0 = acc[i][j][half * 2 + 0] + bia0;
                    float v1 = acc[i][j][half * 2 + 1] + bia1;
                    if (FLAGS & EPI_GELU) {
                        v0 = 0.5f * v0 * (1.f + erff(v0 * 0.70710678118654752f));
                        v1 = 0.5f * v1 * (1.f + erff(v1 * 0.70710678118654752f));
                    }
                    size_t base = (size_t)r * Nc + col;
                    if (FLAGS & EPI_RES) {
                        float2 rr = *(const float2*)(res + base);
                        v0 += rr.x; v1 += rr.y;
                    }
                    float2 o; o.x = v0; o.y = v1;
                    *(float2*)(C + base) = o;
                }
            }
        }
    }
}

// ---------------------------------------------------------------------------
// Attention (unchanged fp32)
// ---------------------------------------------------------------------------
#define AT_TQ 16
#define AT_CK 64
#define SCP   592
#define ATTN_SMEM ((AT_TQ*65 + AT_CK*65 + AT_TQ*SCP) * (int)sizeof(float))

__global__ __launch_bounds__(256) void attn_kernel(
    const float* __restrict__ qkv, float* __restrict__ out)
{
    extern __shared__ float sm[];
    float* qs = sm;
    float* ks = qs + AT_TQ * 65;
    float* sc = ks + AT_CK * 65;

    int bh = blockIdx.y;
    int b = bh >> 4, h = bh & 15;
    int q0 = blockIdx.x * AT_TQ;
    int t = threadIdx.x;

    for (int i = t; i < AT_TQ * HDIM; i += 256) {
        int r = i >> 6, d = i & 63;
        int qi = q0 + r;
        qs[r * 65 + d] = (qi < SEQ)
            ? qkv[((size_t)(b * SEQ + qi)) * (3 * DIM) + h * HDIM + d] : 0.f;
    }

    int rb = (t >> 5) * 2;
    int cb = (t & 31) * 2;
    const int nchunk = (SEQ + AT_CK - 1) / AT_CK;

    for (int kc = 0; kc < nchunk; kc++) {
        int jcnt = min(AT_CK, SEQ - kc * AT_CK);
        __syncthreads();
        for (int i = t; i < AT_CK * HDIM; i += 256) {
            int j = i >> 6, d = i & 63;
            int jg = kc * AT_CK + j;
            ks[j * 65 + d] = (jg < SEQ)
                ? qkv[((size_t)(b * SEQ + jg)) * (3 * DIM) + DIM + h * HDIM + d] : 0.f;
        }
        __syncthreads();
        float s00 = 0.f, s01 = 0.f, s10 = 0.f, s11 = 0.f;
        #pragma unroll 16
        for (int d = 0; d < HDIM; d++) {
            float qa = qs[rb * 65 + d], qb = qs[(rb + 1) * 65 + d];
            float ka = ks[cb * 65 + d], kb = ks[(cb + 1) * 65 + d];
            s00 = fmaf(qa, ka, s00); s01 = fmaf(qa, kb, s01);
            s10 = fmaf(qb, ka, s10); s11 = fmaf(qb, kb, s11);
        }
        int jg0 = kc * AT_CK + cb;
        if (cb < jcnt) {
            sc[rb * SCP + jg0]       = s00 * SCALE;
            sc[(rb + 1) * SCP + jg0] = s10 * SCALE;
        }
        if (cb + 1 < jcnt) {
            sc[rb * SCP + jg0 + 1]       = s01 * SCALE;
            sc[(rb + 1) * SCP + jg0 + 1] = s11 * SCALE;
        }
    }
    __syncthreads();

    {
        int r = t >> 4, l = t & 15;
        float m = -1e30f;
        for (int j = l; j < SEQ; j += 16) m = fmaxf(m, sc[r * SCP + j]);
        #pragma unroll
        for (int o = 8; o > 0; o >>= 1) m = fmaxf(m, __shfl_xor_sync(0xffffffffu, m, o, 16));
        float ssum = 0.f;
        for (int j = l; j < SEQ; j += 16) {
            float e = __expf(sc[r * SCP + j] - m);
            sc[r * SCP + j] = e;
            ssum += e;
        }
        #pragma unroll
        for (int o = 8; o > 0; o >>= 1) ssum += __shfl_xor_sync(0xffffffffu, ssum, o, 16);
        float inv = 1.f / ssum;
        for (int j = l; j < SCP; j += 16)
            sc[r * SCP + j] = (j < SEQ) ? sc[r * SCP + j] * inv : 0.f;
    }

    float a00 = 0.f, a01 = 0.f, a10 = 0.f, a11 = 0.f;
    for (int kc = 0; kc < nchunk; kc++) {
        int jcnt = min(AT_CK, SEQ - kc * AT_CK);
        __syncthreads();
        for (int i = t; i < AT_CK * HDIM; i += 256) {
            int j = i >> 6, d = i & 63;
            int jg = kc * AT_CK + j;
            ks[j * 65 + d] = (jg < SEQ)
                ? qkv[((size_t)(b * SEQ + jg)) * (3 * DIM) + 2 * DIM + h * HDIM + d] : 0.f;
        }
        __syncthreads();
        int jbase = kc * AT_CK;
        for (int jj = 0; jj < jcnt; jj++) {
            float p0 = sc[rb * SCP + jbase + jj];
            float p1 = sc[(rb + 1) * SCP + jbase + jj];
            float v0 = ks[jj * 65 + cb];
            float v1 = ks[jj * 65 + cb + 1];
            a00 = fmaf(p0, v0, a00); a01 = fmaf(p0, v1, a01);
            a10 = fmaf(p1, v0, a10); a11 = fmaf(p1, v1, a11);
        }
    }

    int qi0 = q0 + rb;
    if (qi0 < SEQ) {
        size_t o = (size_t)(b * SEQ + qi0) * DIM + h * HDIM + cb;
        out[o] = a00; out[o + 1] = a01;
    }
    if (qi0 + 1 < SEQ) {
        size_t o = (size_t)(b * SEQ + qi0 + 1) * DIM + h * HDIM + cb;
        out[o] = a10; out[o + 1] = a11;
    }
}

// ---------------------------------------------------------------------------
// Launch
// ---------------------------------------------------------------------------
extern "C" void kernel_launch(void* const* d_in, const int* in_sizes, int n_in,
                              void* d_out, int out_size)
{
    const float* x      = (const float*)d_in[0];
    const float* w_qkv  = (const float*)d_in[1];
    const float* b_qkv  = (const float*)d_in[2];
    const float* w_proj = (const float*)d_in[3];
    const float* b_proj = (const float*)d_in[4];
    const float* ln1_g  = (const float*)d_in[5];
    const float* ln1_b  = (const float*)d_in[6];
    const float* ln2_g  = (const float*)d_in[7];
    const float* ln2_b  = (const float*)d_in[8];
    const float* w_fc1  = (const float*)d_in[9];
    const float* b_fc1  = (const float*)d_in[10];
    const float* w_fc2  = (const float*)d_in[11];
    const float* b_fc2  = (const float*)d_in[12];
    float* out = (float*)d_out;

    float *p_xn, *p_qkv, *p_y, *p_x1, *p_h;
    cudaGetSymbolAddress((void**)&p_xn,  g_xn);
    cudaGetSymbolAddress((void**)&p_qkv, g_qkv);
    cudaGetSymbolAddress((void**)&p_y,   g_y);
    cudaGetSymbolAddress((void**)&p_x1,  g_x1);
    cudaGetSymbolAddress((void**)&p_h,   g_h);

    cudaFuncSetAttribute(attn_kernel,
        cudaFuncAttributeMaxDynamicSharedMemorySize, ATTN_SMEM);

    const int MB = (TOK + 127) / 128;

    ln_kernel<<<TOK, 256>>>(x, ln1_g, ln1_b, p_xn);
    gemm_tf32<EPI_BIAS><<<dim3(3 * DIM / 128, MB), 256>>>(
        p_xn, w_qkv, b_qkv, nullptr, p_qkv, TOK, 3 * DIM, DIM);
    attn_kernel<<<dim3((SEQ + AT_TQ - 1) / AT_TQ, BATCH * HEADS), 256, ATTN_SMEM>>>(
        p_qkv, p_y);
    gemm_tf32<EPI_BIAS | EPI_RES><<<dim3(DIM / 128, MB), 256>>>(
        p_y, w_proj, b_proj, x, p_x1, TOK, DIM, DIM);
    ln_kernel<<<TOK, 256>>>(p_x1, ln2_g, ln2_b, p_xn);
    gemm_tf32<EPI_BIAS | EPI_GELU><<<dim3(HIDDEN / 128, MB), 256>>>(
        p_xn, w_fc1, b_fc1, nullptr, p_h, TOK, HIDDEN, DIM);
    gemm_tf32<EPI_BIAS | EPI_RES><<<dim3(DIM / 128, MB), 256>>>(
        p_h, w_fc2, b_fc2, p_x1, out, TOK, DIM, HIDDEN);
}

// round 3
// speedup vs baseline: 1.8119x; 1.0460x over previous
#include <cuda_runtime.h>
#include <cuda_bf16.h>
#include <math.h>

// ---------------------------------------------------------------------------
// Problem constants
// ---------------------------------------------------------------------------
#define BATCH   16
#define SEQ     577
#define TOK     (BATCH * SEQ)        // 9232
#define DIM     1024
#define HEADS   16
#define HDIM    64
#define HIDDEN  4096
#define EPS     1e-5f
#define SCALE   0.125f

// ---------------------------------------------------------------------------
// Scratch
// ---------------------------------------------------------------------------
__device__ float g_xn [TOK * DIM];
__device__ float g_qkv[TOK * 3 * DIM];
__device__ float g_y  [TOK * DIM];
__device__ float g_x1 [TOK * DIM];
__device__ float g_h  [TOK * HIDDEN];

// ---------------------------------------------------------------------------
// LayerNorm
// ---------------------------------------------------------------------------
__device__ __forceinline__ float block_reduce_sum(float v, float* red) {
    int lane = threadIdx.x & 31, wid = threadIdx.x >> 5;
    #pragma unroll
    for (int o = 16; o > 0; o >>= 1) v += __shfl_xor_sync(0xffffffffu, v, o);
    if (lane == 0) red[wid] = v;
    __syncthreads();
    v = (lane < 8) ? red[lane] : 0.f;
    #pragma unroll
    for (int o = 4; o > 0; o >>= 1) v += __shfl_xor_sync(0xffffffffu, v, o);
    v = __shfl_sync(0xffffffffu, v, 0);
    return v;
}

__global__ __launch_bounds__(256) void ln_kernel(
    const float* __restrict__ x, const float* __restrict__ g,
    const float* __restrict__ b, float* __restrict__ out)
{
    __shared__ float red[8];
    size_t row = blockIdx.x;
    const float4* xr = (const float4*)(x + row * DIM);
    int t = threadIdx.x;
    float4 v = xr[t];
    float s = v.x + v.y + v.z + v.w;
    float mean = block_reduce_sum(s, red) * (1.f / DIM);
    __syncthreads();
    float dx0 = v.x - mean, dx1 = v.y - mean, dx2 = v.z - mean, dx3 = v.w - mean;
    float s2 = dx0*dx0 + dx1*dx1 + dx2*dx2 + dx3*dx3;
    float var = block_reduce_sum(s2, red) * (1.f / DIM);
    float rs = rsqrtf(var + EPS);
    float4 gg = ((const float4*)g)[t];
    float4 bb = ((const float4*)b)[t];
    float4 o;
    o.x = dx0 * rs * gg.x + bb.x;
    o.y = dx1 * rs * gg.y + bb.y;
    o.z = dx2 * rs * gg.z + bb.z;
    o.w = dx3 * rs * gg.w + bb.w;
    ((float4*)(out + row * DIM))[t] = o;
}

// ---------------------------------------------------------------------------
// TF32 GEMM-NT v2: C[M,Nc] = A[M,K] @ B[Nc,K]^T (+bias/gelu/res)
// CTA 256x128x16, 256 threads / 8 warps, warp tile 64x64 (m16n8k8 mma).
// cp.async double-buffered smem, [row][k] layout stride 20 (conflict-free).
// ---------------------------------------------------------------------------
#define EPI_BIAS 1
#define EPI_GELU 2
#define EPI_RES  4

#define GBM 256
#define GBN 128
#define GBK 16
#define RST 20                      // row stride in floats (16 + 4 pad)
#define A_FLOATS (GBM * RST)        // 5120 per buffer
#define B_FLOATS (GBN * RST)        // 2560 per buffer
#define GEMM_SMEM ((2 * A_FLOATS + 2 * B_FLOATS) * (int)sizeof(float))  // 61440

__device__ __forceinline__ void cp_async16(void* smem_dst, const void* gsrc) {
    unsigned s = (unsigned)__cvta_generic_to_shared(smem_dst);
    asm volatile("cp.async.cg.shared.global [%0], [%1], 16;\n" :: "r"(s), "l"(gsrc));
}
__device__ __forceinline__ void cp_commit() {
    asm volatile("cp.async.commit_group;\n");
}
template<int N>
__device__ __forceinline__ void cp_wait() {
    asm volatile("cp.async.wait_group %0;\n" :: "n"(N));
}

__device__ __forceinline__ void mma_tf32(
    float c[4], unsigned a0, unsigned a1, unsigned a2, unsigned a3,
    unsigned b0, unsigned b1)
{
    asm volatile(
        "mma.sync.aligned.m16n8k8.row.col.f32.tf32.tf32.f32 "
        "{%0,%1,%2,%3}, {%4,%5,%6,%7}, {%8,%9}, {%0,%1,%2,%3};\n"
        : "+f"(c[0]), "+f"(c[1]), "+f"(c[2]), "+f"(c[3])
        : "r"(a0), "r"(a1), "r"(a2), "r"(a3), "r"(b0), "r"(b1));
}

template<int FLAGS>
__global__ __launch_bounds__(256, 1) void gemm_tf32(
    const float* __restrict__ A, const float* __restrict__ Bw,
    const float* __restrict__ bias, const float* __restrict__ res,
    float* __restrict__ C, int M, int Nc, int K)
{
    extern __shared__ float sm[];
    // layout: A buf0 | A buf1 | B buf0 | B buf1
    float* Abuf[2] = { sm, sm + A_FLOATS };
    float* Bbuf[2] = { sm + 2 * A_FLOATS, sm + 2 * A_FLOATS + B_FLOATS };

    int tid = threadIdx.x;
    int m0 = blockIdx.y * GBM, n0 = blockIdx.x * GBN;

    int warp = tid >> 5, lane = tid & 31;
    int wm = warp & 3, wn = warp >> 2;     // 4 x 2 warp grid
    int mb = wm * 64, nb = wn * 64;
    int g  = lane >> 2;                    // 0..7
    int tg = lane & 3;                     // 0..3

    // loader coords: each thread owns one 16B chunk column of several rows
    int l_row = tid >> 2;                  // 0..63
    int l_chk = (tid & 3) << 2;            // 0,4,8,12 (float offset)

    float acc[4][8][4];
    #pragma unroll
    for (int i = 0; i < 4; i++)
        #pragma unroll
        for (int j = 0; j < 8; j++)
            #pragma unroll
            for (int c = 0; c < 4; c++) acc[i][j][c] = 0.f;

    const int T = K / GBK;

    // precomputed global row bases (A rows clamped for OOB tiles)
    int arow[4];
    #pragma unroll
    for (int r = 0; r < 4; r++) {
        int rr = m0 + l_row + 64 * r;
        arow[r] = rr < M ? rr : M - 1;
    }

    // ---- prologue: fill buffer 0 ----
    {
        int k0 = 0;
        #pragma unroll
        for (int r = 0; r < 4; r++)
            cp_async16(&Abuf[0][(l_row + 64 * r) * RST + l_chk],
                       A + (size_t)arow[r] * K + k0 + l_chk);
        #pragma unroll
        for (int r = 0; r < 2; r++)
            cp_async16(&Bbuf[0][(l_row + 64 * r) * RST + l_chk],
                       Bw + (size_t)(n0 + l_row + 64 * r) * K + k0 + l_chk);
        cp_commit();
    }

    for (int t = 0; t < T; t++) {
        int buf = t & 1;
        if (t + 1 < T) {
            int k0 = (t + 1) * GBK;
            int nb2 = buf ^ 1;
            #pragma unroll
            for (int r = 0; r < 4; r++)
                cp_async16(&Abuf[nb2][(l_row + 64 * r) * RST + l_chk],
                           A + (size_t)arow[r] * K + k0 + l_chk);
            #pragma unroll
            for (int r = 0; r < 2; r++)
                cp_async16(&Bbuf[nb2][(l_row + 64 * r) * RST + l_chk],
                           Bw + (size_t)(n0 + l_row + 64 * r) * K + k0 + l_chk);
            cp_commit();
            cp_wait<1>();
        } else {
            cp_wait<0>();
        }
        __syncthreads();

        const float* as = Abuf[buf];
        const float* bs = Bbuf[buf];
        #pragma unroll
        for (int ks = 0; ks < 2; ks++) {
            int kk = ks * 8;
            unsigned a[4][4];
            #pragma unroll
            for (int i = 0; i < 4; i++) {
                int r0 = (mb + i * 16 + g) * RST + kk + tg;
                a[i][0] = __float_as_uint(as[r0]);
                a[i][1] = __float_as_uint(as[r0 + 8 * RST]);
                a[i][2] = __float_as_uint(as[r0 + 4]);
                a[i][3] = __float_as_uint(as[r0 + 8 * RST + 4]);
            }
            #pragma unroll
            for (int j = 0; j < 8; j++) {
                int c0 = (nb + j * 8 + g) * RST + kk + tg;
                unsigned b0 = __float_as_uint(bs[c0]);
                unsigned b1 = __float_as_uint(bs[c0 + 4]);
                #pragma unroll
                for (int i = 0; i < 4; i++)
                    mma_tf32(acc[i][j], a[i][0], a[i][1], a[i][2], a[i][3], b0, b1);
            }
        }
        __syncthreads();
    }

    // ---- epilogue ----
    #pragma unroll
    for (int i = 0; i < 4; i++) {
        #pragma unroll
        for (int j = 0; j < 8; j++) {
            int row0 = m0 + mb + i * 16 + g;
            int col  = n0 + nb + j * 8 + tg * 2;
            float bia0 = 0.f, bia1 = 0.f;
            if (FLAGS & EPI_BIAS) { bia0 = bias[col]; bia1 = bias[col + 1]; }
            #pragma unroll
            for (int half = 0; half < 2; half++) {
                int r = row0 + half * 8;
                if (r < M) {
                    float v0 = acc[i][j][half * 2 + 0] + bia0;
                    float v1 = acc[i][j][half * 2 + 1] + bia1;
                    if (FLAGS & EPI_GELU) {
                        v0 = 0.5f * v0 * (1.f + erff(v0 * 0.70710678118654752f));
                        v1 = 0.5f * v1 * (1.f + erff(v1 * 0.70710678118654752f));
                    }
                    size_t base = (size_t)r * Nc + col;
                    if (FLAGS & EPI_RES) {
                        float2 rr = *(const float2*)(res + base);
                        v0 += rr.x; v1 += rr.y;
                    }
                    float2 o; o.x = v0; o.y = v1;
                    *(float2*)(C + base) = o;
                }
            }
        }
    }
}

// ---------------------------------------------------------------------------
// Attention (fp32, unchanged)
// ---------------------------------------------------------------------------
#define AT_TQ 16
#define AT_CK 64
#define SCP   592
#define ATTN_SMEM ((AT_TQ*65 + AT_CK*65 + AT_TQ*SCP) * (int)sizeof(float))

__global__ __launch_bounds__(256) void attn_kernel(
    const float* __restrict__ qkv, float* __restrict__ out)
{
    extern __shared__ float sm[];
    float* qs = sm;
    float* ks = qs + AT_TQ * 65;
    float* sc = ks + AT_CK * 65;

    int bh = blockIdx.y;
    int b = bh >> 4, h = bh & 15;
    int q0 = blockIdx.x * AT_TQ;
    int t = threadIdx.x;

    for (int i = t; i < AT_TQ * HDIM; i += 256) {
        int r = i >> 6, d = i & 63;
        int qi = q0 + r;
        qs[r * 65 + d] = (qi < SEQ)
            ? qkv[((size_t)(b * SEQ + qi)) * (3 * DIM) + h * HDIM + d] : 0.f;
    }

    int rb = (t >> 5) * 2;
    int cb = (t & 31) * 2;
    const int nchunk = (SEQ + AT_CK - 1) / AT_CK;

    for (int kc = 0; kc < nchunk; kc++) {
        int jcnt = min(AT_CK, SEQ - kc * AT_CK);
        __syncthreads();
        for (int i = t; i < AT_CK * HDIM; i += 256) {
            int j = i >> 6, d = i & 63;
            int jg = kc * AT_CK + j;
            ks[j * 65 + d] = (jg < SEQ)
                ? qkv[((size_t)(b * SEQ + jg)) * (3 * DIM) + DIM + h * HDIM + d] : 0.f;
        }
        __syncthreads();
        float s00 = 0.f, s01 = 0.f, s10 = 0.f, s11 = 0.f;
        #pragma unroll 16
        for (int d = 0; d < HDIM; d++) {
            float qa = qs[rb * 65 + d], qb = qs[(rb + 1) * 65 + d];
            float ka = ks[cb * 65 + d], kb = ks[(cb + 1) * 65 + d];
            s00 = fmaf(qa, ka, s00); s01 = fmaf(qa, kb, s01);
            s10 = fmaf(qb, ka, s10); s11 = fmaf(qb, kb, s11);
        }
        int jg0 = kc * AT_CK + cb;
        if (cb < jcnt) {
            sc[rb * SCP + jg0]       = s00 * SCALE;
            sc[(rb + 1) * SCP + jg0] = s10 * SCALE;
        }
        if (cb + 1 < jcnt) {
            sc[rb * SCP + jg0 + 1]       = s01 * SCALE;
            sc[(rb + 1) * SCP + jg0 + 1] = s11 * SCALE;
        }
    }
    __syncthreads();

    {
        int r = t >> 4, l = t & 15;
        float m = -1e30f;
        for (int j = l; j < SEQ; j += 16) m = fmaxf(m, sc[r * SCP + j]);
        #pragma unroll
        for (int o = 8; o > 0; o >>= 1) m = fmaxf(m, __shfl_xor_sync(0xffffffffu, m, o, 16));
        float ssum = 0.f;
        for (int j = l; j < SEQ; j += 16) {
            float e = __expf(sc[r * SCP + j] - m);
            sc[r * SCP + j] = e;
            ssum += e;
        }
        #pragma unroll
        for (int o = 8; o > 0; o >>= 1) ssum += __shfl_xor_sync(0xffffffffu, ssum, o, 16);
        float inv = 1.f / ssum;
        for (int j = l; j < SCP; j += 16)
            sc[r * SCP + j] = (j < SEQ) ? sc[r * SCP + j] * inv : 0.f;
    }

    float a00 = 0.f, a01 = 0.f, a10 = 0.f, a11 = 0.f;
    for (int kc = 0; kc < nchunk; kc++) {
        int jcnt = min(AT_CK, SEQ - kc * AT_CK);
        __syncthreads();
        for (int i = t; i < AT_CK * HDIM; i += 256) {
            int j = i >> 6, d = i & 63;
            int jg = kc * AT_CK + j;
            ks[j * 65 + d] = (jg < SEQ)
                ? qkv[((size_t)(b * SEQ + jg)) * (3 * DIM) + 2 * DIM + h * HDIM + d] : 0.f;
        }
        __syncthreads();
        int jbase = kc * AT_CK;
        for (int jj = 0; jj < jcnt; jj++) {
            float p0 = sc[rb * SCP + jbase + jj];
            float p1 = sc[(rb + 1) * SCP + jbase + jj];
            float v0 = ks[jj * 65 + cb];
            float v1 = ks[jj * 65 + cb + 1];
            a00 = fmaf(p0, v0, a00); a01 = fmaf(p0, v1, a01);
            a10 = fmaf(p1, v0, a10); a11 = fmaf(p1, v1, a11);
        }
    }

    int qi0 = q0 + rb;
    if (qi0 < SEQ) {
        size_t o = (size_t)(b * SEQ + qi0) * DIM + h * HDIM + cb;
        out[o] = a00; out[o + 1] = a01;
    }
    if (qi0 + 1 < SEQ) {
        size_t o = (size_t)(b * SEQ + qi0 + 1) * DIM + h * HDIM + cb;
        out[o] = a10; out[o + 1] = a11;
    }
}

// ---------------------------------------------------------------------------
// Launch
// ---------------------------------------------------------------------------
extern "C" void kernel_launch(void* const* d_in, const int* in_sizes, int n_in,
                              void* d_out, int out_size)
{
    const float* x      = (const float*)d_in[0];
    const float* w_qkv  = (const float*)d_in[1];
    const float* b_qkv  = (const float*)d_in[2];
    const float* w_proj = (const float*)d_in[3];
    const float* b_proj = (const float*)d_in[4];
    const float* ln1_g  = (const float*)d_in[5];
    const float* ln1_b  = (const float*)d_in[6];
    const float* ln2_g  = (const float*)d_in[7];
    const float* ln2_b  = (const float*)d_in[8];
    const float* w_fc1  = (const float*)d_in[9];
    const float* b_fc1  = (const float*)d_in[10];
    const float* w_fc2  = (const float*)d_in[11];
    const float* b_fc2  = (const float*)d_in[12];
    float* out = (float*)d_out;

    float *p_xn, *p_qkv, *p_y, *p_x1, *p_h;
    cudaGetSymbolAddress((void**)&p_xn,  g_xn);
    cudaGetSymbolAddress((void**)&p_qkv, g_qkv);
    cudaGetSymbolAddress((void**)&p_y,   g_y);
    cudaGetSymbolAddress((void**)&p_x1,  g_x1);
    cudaGetSymbolAddress((void**)&p_h,   g_h);

    cudaFuncSetAttribute(attn_kernel,
        cudaFuncAttributeMaxDynamicSharedMemorySize, ATTN_SMEM);
    cudaFuncSetAttribute(gemm_tf32<EPI_BIAS>,
        cudaFuncAttributeMaxDynamicSharedMemorySize, GEMM_SMEM);
    cudaFuncSetAttribute(gemm_tf32<EPI_BIAS | EPI_RES>,
        cudaFuncAttributeMaxDynamicSharedMemorySize, GEMM_SMEM);
    cudaFuncSetAttribute(gemm_tf32<EPI_BIAS | EPI_GELU>,
        cudaFuncAttributeMaxDynamicSharedMemorySize, GEMM_SMEM);

    const int MB = (TOK + GBM - 1) / GBM;   // 37

    ln_kernel<<<TOK, 256>>>(x, ln1_g, ln1_b, p_xn);
    gemm_tf32<EPI_BIAS><<<dim3(3 * DIM / GBN, MB), 256, GEMM_SMEM>>>(
        p_xn, w_qkv, b_qkv, nullptr, p_qkv, TOK, 3 * DIM, DIM);
    attn_kernel<<<dim3((SEQ + AT_TQ - 1) / AT_TQ, BATCH * HEADS), 256, ATTN_SMEM>>>(
        p_qkv, p_y);
    gemm_tf32<EPI_BIAS | EPI_RES><<<dim3(DIM / GBN, MB), 256, GEMM_SMEM>>>(
        p_y, w_proj, b_proj, x, p_x1, TOK, DIM, DIM);
    ln_kernel<<<TOK, 256>>>(p_x1, ln2_g, ln2_b, p_xn);
    gemm_tf32<EPI_BIAS | EPI_GELU><<<dim3(HIDDEN / GBN, MB), 256, GEMM_SMEM>>>(
        p_xn, w_fc1, b_fc1, nullptr, p_h, TOK, HIDDEN, DIM);
    gemm_tf32<EPI_BIAS | EPI_RES><<<dim3(DIM / GBN, MB), 256, GEMM_SMEM>>>(
        p_h, w_fc2, b_fc2, p_x1, out, TOK, DIM, HIDDEN);
}

// round 4
// speedup vs baseline: 2.3034x; 1.2713x over previous
#include <cuda_runtime.h>
#include <cuda_bf16.h>
#include <math.h>

// ---------------------------------------------------------------------------
// Problem constants
// ---------------------------------------------------------------------------
#define BATCH   16
#define SEQ     577
#define TOK     (BATCH * SEQ)        // 9232
#define DIM     1024
#define HEADS   16
#define HDIM    64
#define HIDDEN  4096
#define EPS     1e-5f
#define SCALE   0.125f

// ---------------------------------------------------------------------------
// Scratch
// ---------------------------------------------------------------------------
__device__ float g_xn [TOK * DIM];
__device__ float g_qkv[TOK * 3 * DIM];
__device__ float g_y  [TOK * DIM];
__device__ float g_x1 [TOK * DIM];
__device__ float g_h  [TOK * HIDDEN];

// ---------------------------------------------------------------------------
// Common helpers
// ---------------------------------------------------------------------------
__device__ __forceinline__ unsigned f2tf32(float f) {
    unsigned u;
    asm("cvt.rna.tf32.f32 %0, %1;" : "=r"(u) : "f"(f));
    return u;
}
__device__ __forceinline__ float tf32r(float f) {
    return __uint_as_float(f2tf32(f));
}
__device__ __forceinline__ void mma_tf32(
    float c[4], unsigned a0, unsigned a1, unsigned a2, unsigned a3,
    unsigned b0, unsigned b1)
{
    asm volatile(
        "mma.sync.aligned.m16n8k8.row.col.f32.tf32.tf32.f32 "
        "{%0,%1,%2,%3}, {%4,%5,%6,%7}, {%8,%9}, {%0,%1,%2,%3};\n"
        : "+f"(c[0]), "+f"(c[1]), "+f"(c[2]), "+f"(c[3])
        : "r"(a0), "r"(a1), "r"(a2), "r"(a3), "r"(b0), "r"(b1));
}

// ---------------------------------------------------------------------------
// LayerNorm
// ---------------------------------------------------------------------------
__device__ __forceinline__ float block_reduce_sum(float v, float* red) {
    int lane = threadIdx.x & 31, wid = threadIdx.x >> 5;
    #pragma unroll
    for (int o = 16; o > 0; o >>= 1) v += __shfl_xor_sync(0xffffffffu, v, o);
    if (lane == 0) red[wid] = v;
    __syncthreads();
    v = (lane < 8) ? red[lane] : 0.f;
    #pragma unroll
    for (int o = 4; o > 0; o >>= 1) v += __shfl_xor_sync(0xffffffffu, v, o);
    v = __shfl_sync(0xffffffffu, v, 0);
    return v;
}

__global__ __launch_bounds__(256) void ln_kernel(
    const float* __restrict__ x, const float* __restrict__ g,
    const float* __restrict__ b, float* __restrict__ out)
{
    __shared__ float red[8];
    size_t row = blockIdx.x;
    const float4* xr = (const float4*)(x + row * DIM);
    int t = threadIdx.x;
    float4 v = xr[t];
    float s = v.x + v.y + v.z + v.w;
    float mean = block_reduce_sum(s, red) * (1.f / DIM);
    __syncthreads();
    float dx0 = v.x - mean, dx1 = v.y - mean, dx2 = v.z - mean, dx3 = v.w - mean;
    float s2 = dx0*dx0 + dx1*dx1 + dx2*dx2 + dx3*dx3;
    float var = block_reduce_sum(s2, red) * (1.f / DIM);
    float rs = rsqrtf(var + EPS);
    float4 gg = ((const float4*)g)[t];
    float4 bb = ((const float4*)b)[t];
    float4 o;
    o.x = dx0 * rs * gg.x + bb.x;
    o.y = dx1 * rs * gg.y + bb.y;
    o.z = dx2 * rs * gg.z + bb.z;
    o.w = dx3 * rs * gg.w + bb.w;
    ((float4*)(out + row * DIM))[t] = o;
}

// ---------------------------------------------------------------------------
// TF32 GEMM-NT: 256x128x16 CTA, cp.async double buffer, cvt at fragment load
// ---------------------------------------------------------------------------
#define EPI_BIAS 1
#define EPI_GELU 2
#define EPI_RES  4

#define GBM 256
#define GBN 128
#define GBK 16
#define RST 20
#define A_FLOATS (GBM * RST)
#define B_FLOATS (GBN * RST)
#define GEMM_SMEM ((2 * A_FLOATS + 2 * B_FLOATS) * (int)sizeof(float))

__device__ __forceinline__ void cp_async16(void* smem_dst, const void* gsrc) {
    unsigned s = (unsigned)__cvta_generic_to_shared(smem_dst);
    asm volatile("cp.async.cg.shared.global [%0], [%1], 16;\n" :: "r"(s), "l"(gsrc));
}
__device__ __forceinline__ void cp_commit() {
    asm volatile("cp.async.commit_group;\n");
}
template<int N>
__device__ __forceinline__ void cp_wait() {
    asm volatile("cp.async.wait_group %0;\n" :: "n"(N));
}

template<int FLAGS>
__global__ __launch_bounds__(256, 1) void gemm_tf32(
    const float* __restrict__ A, const float* __restrict__ Bw,
    const float* __restrict__ bias, const float* __restrict__ res,
    float* __restrict__ C, int M, int Nc, int K)
{
    extern __shared__ float sm[];
    float* Abuf[2] = { sm, sm + A_FLOATS };
    float* Bbuf[2] = { sm + 2 * A_FLOATS, sm + 2 * A_FLOATS + B_FLOATS };

    int tid = threadIdx.x;
    int m0 = blockIdx.y * GBM, n0 = blockIdx.x * GBN;

    int warp = tid >> 5, lane = tid & 31;
    int wm = warp & 3, wn = warp >> 2;
    int mb = wm * 64, nb = wn * 64;
    int g  = lane >> 2;
    int tg = lane & 3;

    int l_row = tid >> 2;
    int l_chk = (tid & 3) << 2;

    float acc[4][8][4];
    #pragma unroll
    for (int i = 0; i < 4; i++)
        #pragma unroll
        for (int j = 0; j < 8; j++)
            #pragma unroll
            for (int c = 0; c < 4; c++) acc[i][j][c] = 0.f;

    const int T = K / GBK;

    int arow[4];
    #pragma unroll
    for (int r = 0; r < 4; r++) {
        int rr = m0 + l_row + 64 * r;
        arow[r] = rr < M ? rr : M - 1;
    }

    {
        #pragma unroll
        for (int r = 0; r < 4; r++)
            cp_async16(&Abuf[0][(l_row + 64 * r) * RST + l_chk],
                       A + (size_t)arow[r] * K + l_chk);
        #pragma unroll
        for (int r = 0; r < 2; r++)
            cp_async16(&Bbuf[0][(l_row + 64 * r) * RST + l_chk],
                       Bw + (size_t)(n0 + l_row + 64 * r) * K + l_chk);
        cp_commit();
    }

    for (int t = 0; t < T; t++) {
        int buf = t & 1;
        if (t + 1 < T) {
            int k0 = (t + 1) * GBK;
            int nb2 = buf ^ 1;
            #pragma unroll
            for (int r = 0; r < 4; r++)
                cp_async16(&Abuf[nb2][(l_row + 64 * r) * RST + l_chk],
                           A + (size_t)arow[r] * K + k0 + l_chk);
            #pragma unroll
            for (int r = 0; r < 2; r++)
                cp_async16(&Bbuf[nb2][(l_row + 64 * r) * RST + l_chk],
                           Bw + (size_t)(n0 + l_row + 64 * r) * K + k0 + l_chk);
            cp_commit();
            cp_wait<1>();
        } else {
            cp_wait<0>();
        }
        __syncthreads();

        const float* as = Abuf[buf];
        const float* bs = Bbuf[buf];
        #pragma unroll
        for (int ks = 0; ks < 2; ks++) {
            int kk = ks * 8;
            unsigned a[4][4];
            #pragma unroll
            for (int i = 0; i < 4; i++) {
                int r0 = (mb + i * 16 + g) * RST + kk + tg;
                a[i][0] = f2tf32(as[r0]);
                a[i][1] = f2tf32(as[r0 + 8 * RST]);
                a[i][2] = f2tf32(as[r0 + 4]);
                a[i][3] = f2tf32(as[r0 + 8 * RST + 4]);
            }
            #pragma unroll
            for (int j = 0; j < 8; j++) {
                int c0 = (nb + j * 8 + g) * RST + kk + tg;
                unsigned b0 = f2tf32(bs[c0]);
                unsigned b1 = f2tf32(bs[c0 + 4]);
                #pragma unroll
                for (int i = 0; i < 4; i++)
                    mma_tf32(acc[i][j], a[i][0], a[i][1], a[i][2], a[i][3], b0, b1);
            }
        }
        __syncthreads();
    }

    #pragma unroll
    for (int i = 0; i < 4; i++) {
        #pragma unroll
        for (int j = 0; j < 8; j++) {
            int row0 = m0 + mb + i * 16 + g;
            int col  = n0 + nb + j * 8 + tg * 2;
            float bia0 = 0.f, bia1 = 0.f;
            if (FLAGS & EPI_BIAS) { bia0 = bias[col]; bia1 = bias[col + 1]; }
            #pragma unroll
            for (int half = 0; half < 2; half++) {
                int r = row0 + half * 8;
                if (r < M) {
                    float v0 = acc[i][j][half * 2 + 0] + bia0;
                    float v1 = acc[i][j][half * 2 + 1] + bia1;
                    if (FLAGS & EPI_GELU) {
                        v0 = 0.5f * v0 * (1.f + erff(v0 * 0.70710678118654752f));
                        v1 = 0.5f * v1 * (1.f + erff(v1 * 0.70710678118654752f));
                    }
                    size_t base = (size_t)r * Nc + col;
                    if (FLAGS & EPI_RES) {
                        float2 rr = *(const float2*)(res + base);
                        v0 += rr.x; v1 += rr.y;
                    }
                    float2 o; o.x = v0; o.y = v1;
                    *(float2*)(C + base) = o;
                }
            }
        }
    }
}

// ---------------------------------------------------------------------------
// Attention v2: tensor-core (tf32 mma), 64 queries/CTA, full score row in smem
// Strides chosen for conflict-free fragment access:
//   Q/K stride 84 (mod32=20: pattern 20g+tg distinct), V stride 72 (mod32=8:
//   pattern 8tg+g distinct), S stride 660 (mod32=20).
// ---------------------------------------------------------------------------
#define FQ   64
#define FC   64
#define NCH  10                 // ceil(577/64)
#define QST  84
#define KST  84
#define VST  72
#define SST  660
#define ATT_Q_OFF 0
#define ATT_K_OFF (FQ * QST)                    // 5376
#define ATT_V_OFF (ATT_K_OFF + FC * KST)        // 10752
#define ATT_S_OFF (ATT_V_OFF + FC * VST)        // 15360
#define ATT2_SMEM ((ATT_S_OFF + FQ * SST) * (int)sizeof(float))  // 230400

__global__ __launch_bounds__(256, 1) void attn2_kernel(
    const float* __restrict__ qkv, float* __restrict__ out)
{
    extern __shared__ float sm[];
    float* qs = sm + ATT_Q_OFF;
    float* ks = sm + ATT_K_OFF;
    float* vs = sm + ATT_V_OFF;
    float* sc = sm + ATT_S_OFF;

    int bh = blockIdx.y;
    int b = bh >> 4, h = bh & 15;
    int q0 = blockIdx.x * FQ;
    int t = threadIdx.x;
    int warp = t >> 5, lane = t & 31;
    int g = lane >> 2, tg = lane & 3;
    int mb = (warp & 3) * 16;
    int nb = (warp >> 2) * 32;

    // ---- load Q tile (tf32-rounded) ----
    for (int idx = t; idx < FQ * 16; idx += 256) {
        int r = idx >> 4, c4 = (idx & 15) << 2;
        int qr = q0 + r; if (qr >= SEQ) qr = SEQ - 1;
        float4 v = *(const float4*)(qkv + (size_t)(b * SEQ + qr) * (3 * DIM) + h * HDIM + c4);
        qs[r * QST + c4 + 0] = tf32r(v.x);
        qs[r * QST + c4 + 1] = tf32r(v.y);
        qs[r * QST + c4 + 2] = tf32r(v.z);
        qs[r * QST + c4 + 3] = tf32r(v.w);
    }

    float oacc[4][4];
    #pragma unroll
    for (int j = 0; j < 4; j++)
        #pragma unroll
        for (int c = 0; c < 4; c++) oacc[j][c] = 0.f;

    // ---- pass 1: S = Q @ K^T * SCALE ----
    for (int c = 0; c < NCH; c++) {
        __syncthreads();
        for (int idx = t; idx < FC * 16; idx += 256) {
            int r = idx >> 4, c4 = (idx & 15) << 2;
            int kr = c * FC + r;
            if (kr < SEQ) {
                float4 v = *(const float4*)(qkv + (size_t)(b * SEQ + kr) * (3 * DIM) + DIM + h * HDIM + c4);
                ks[r * KST + c4 + 0] = tf32r(v.x);
                ks[r * KST + c4 + 1] = tf32r(v.y);
                ks[r * KST + c4 + 2] = tf32r(v.z);
                ks[r * KST + c4 + 3] = tf32r(v.w);
            } else {
                ks[r * KST + c4 + 0] = 0.f;
                ks[r * KST + c4 + 1] = 0.f;
                ks[r * KST + c4 + 2] = 0.f;
                ks[r * KST + c4 + 3] = 0.f;
            }
        }
        __syncthreads();

        float sacc[4][4];
        #pragma unroll
        for (int j = 0; j < 4; j++)
            #pragma unroll
            for (int cc = 0; cc < 4; cc++) sacc[j][cc] = 0.f;

        #pragma unroll
        for (int k8 = 0; k8 < 8; k8++) {
            int kk = k8 * 8;
            unsigned a0 = __float_as_uint(qs[(mb + g) * QST + kk + tg]);
            unsigned a1 = __float_as_uint(qs[(mb + 8 + g) * QST + kk + tg]);
            unsigned a2 = __float_as_uint(qs[(mb + g) * QST + kk + tg + 4]);
            unsigned a3 = __float_as_uint(qs[(mb + 8 + g) * QST + kk + tg + 4]);
            #pragma unroll
            for (int j = 0; j < 4; j++) {
                unsigned b0 = __float_as_uint(ks[(nb + 8 * j + g) * KST + kk + tg]);
                unsigned b1 = __float_as_uint(ks[(nb + 8 * j + g) * KST + kk + tg + 4]);
                mma_tf32(sacc[j], a0, a1, a2, a3, b0, b1);
            }
        }

        #pragma unroll
        for (int j = 0; j < 4; j++) {
            int cc = c * FC + nb + 8 * j + 2 * tg;
            int r0 = mb + g, r1 = r0 + 8;
            sc[r0 * SST + cc]     = (cc     < SEQ) ? sacc[j][0] * SCALE : 0.f;
            sc[r0 * SST + cc + 1] = (cc + 1 < SEQ) ? sacc[j][1] * SCALE : 0.f;
            sc[r1 * SST + cc]     = (cc     < SEQ) ? sacc[j][2] * SCALE : 0.f;
            sc[r1 * SST + cc + 1] = (cc + 1 < SEQ) ? sacc[j][3] * SCALE : 0.f;
        }
    }
    __syncthreads();

    // ---- softmax: 4 threads per row ----
    {
        int r = t >> 2, l = t & 3;
        float* row = sc + r * SST;
        float m = -1e30f;
        for (int j = l; j < SEQ; j += 4) m = fmaxf(m, row[j]);
        m = fmaxf(m, __shfl_xor_sync(0xffffffffu, m, 1, 4));
        m = fmaxf(m, __shfl_xor_sync(0xffffffffu, m, 2, 4));
        float s = 0.f;
        for (int j = l; j < SEQ; j += 4) {
            float e = __expf(row[j] - m);
            row[j] = e;
            s += e;
        }
        s += __shfl_xor_sync(0xffffffffu, s, 1, 4);
        s += __shfl_xor_sync(0xffffffffu, s, 2, 4);
        float inv = 1.f / s;
        for (int j = l; j < SEQ; j += 4) row[j] = tf32r(row[j] * inv);
    }

    // ---- pass 2: O = P @ V ----
    for (int c = 0; c < NCH; c++) {
        __syncthreads();
        for (int idx = t; idx < FC * 16; idx += 256) {
            int r = idx >> 4, c4 = (idx & 15) << 2;
            int vr = c * FC + r;
            if (vr < SEQ) {
                float4 v = *(const float4*)(qkv + (size_t)(b * SEQ + vr) * (3 * DIM) + 2 * DIM + h * HDIM + c4);
                vs[r * VST + c4 + 0] = tf32r(v.x);
                vs[r * VST + c4 + 1] = tf32r(v.y);
                vs[r * VST + c4 + 2] = tf32r(v.z);
                vs[r * VST + c4 + 3] = tf32r(v.w);
            } else {
                vs[r * VST + c4 + 0] = 0.f;
                vs[r * VST + c4 + 1] = 0.f;
                vs[r * VST + c4 + 2] = 0.f;
                vs[r * VST + c4 + 3] = 0.f;
            }
        }
        __syncthreads();

        #pragma unroll
        for (int k8 = 0; k8 < 8; k8++) {
            int kk = k8 * 8;
            int gc = c * FC + kk;
            unsigned a0 = __float_as_uint(sc[(mb + g) * SST + gc + tg]);
            unsigned a1 = __float_as_uint(sc[(mb + 8 + g) * SST + gc + tg]);
            unsigned a2 = __float_as_uint(sc[(mb + g) * SST + gc + tg + 4]);
            unsigned a3 = __float_as_uint(sc[(mb + 8 + g) * SST + gc + tg + 4]);
            #pragma unroll
            for (int j = 0; j < 4; j++) {
                unsigned b0 = __float_as_uint(vs[(kk + tg) * VST + nb + 8 * j + g]);
                unsigned b1 = __float_as_uint(vs[(kk + tg + 4) * VST + nb + 8 * j + g]);
                mma_tf32(oacc[j], a0, a1, a2, a3, b0, b1);
            }
        }
    }

    // ---- store O ----
    #pragma unroll
    for (int j = 0; j < 4; j++) {
        int col = h * HDIM + nb + 8 * j + 2 * tg;
        int r0 = q0 + mb + g, r1 = r0 + 8;
        if (r0 < SEQ) {
            float2 o; o.x = oacc[j][0]; o.y = oacc[j][1];
            *(float2*)(out + (size_t)(b * SEQ + r0) * DIM + col) = o;
        }
        if (r1 < SEQ) {
            float2 o; o.x = oacc[j][2]; o.y = oacc[j][3];
            *(float2*)(out + (size_t)(b * SEQ + r1) * DIM + col) = o;
        }
    }
}

// ---------------------------------------------------------------------------
// Launch
// ---------------------------------------------------------------------------
extern "C" void kernel_launch(void* const* d_in, const int* in_sizes, int n_in,
                              void* d_out, int out_size)
{
    const float* x      = (const float*)d_in[0];
    const float* w_qkv  = (const float*)d_in[1];
    const float* b_qkv  = (const float*)d_in[2];
    const float* w_proj = (const float*)d_in[3];
    const float* b_proj = (const float*)d_in[4];
    const float* ln1_g  = (const float*)d_in[5];
    const float* ln1_b  = (const float*)d_in[6];
    const float* ln2_g  = (const float*)d_in[7];
    const float* ln2_b  = (const float*)d_in[8];
    const float* w_fc1  = (const float*)d_in[9];
    const float* b_fc1  = (const float*)d_in[10];
    const float* w_fc2  = (const float*)d_in[11];
    const float* b_fc2  = (const float*)d_in[12];
    float* out = (float*)d_out;

    float *p_xn, *p_qkv, *p_y, *p_x1, *p_h;
    cudaGetSymbolAddress((void**)&p_xn,  g_xn);
    cudaGetSymbolAddress((void**)&p_qkv, g_qkv);
    cudaGetSymbolAddress((void**)&p_y,   g_y);
    cudaGetSymbolAddress((void**)&p_x1,  g_x1);
    cudaGetSymbolAddress((void**)&p_h,   g_h);

    cudaFuncSetAttribute(attn2_kernel,
        cudaFuncAttributeMaxDynamicSharedMemorySize, ATT2_SMEM);
    cudaFuncSetAttribute(gemm_tf32<EPI_BIAS>,
        cudaFuncAttributeMaxDynamicSharedMemorySize, GEMM_SMEM);
    cudaFuncSetAttribute(gemm_tf32<EPI_BIAS | EPI_RES>,
        cudaFuncAttributeMaxDynamicSharedMemorySize, GEMM_SMEM);
    cudaFuncSetAttribute(gemm_tf32<EPI_BIAS | EPI_GELU>,
        cudaFuncAttributeMaxDynamicSharedMemorySize, GEMM_SMEM);

    const int MB = (TOK + GBM - 1) / GBM;   // 37

    ln_kernel<<<TOK, 256>>>(x, ln1_g, ln1_b, p_xn);
    gemm_tf32<EPI_BIAS><<<dim3(3 * DIM / GBN, MB), 256, GEMM_SMEM>>>(
        p_xn, w_qkv, b_qkv, nullptr, p_qkv, TOK, 3 * DIM, DIM);
    attn2_kernel<<<dim3((SEQ + FQ - 1) / FQ, BATCH * HEADS), 256, ATT2_SMEM>>>(
        p_qkv, p_y);
    gemm_tf32<EPI_BIAS | EPI_RES><<<dim3(DIM / GBN, MB), 256, GEMM_SMEM>>>(
        p_y, w_proj, b_proj, x, p_x1, TOK, DIM, DIM);
    ln_kernel<<<TOK, 256>>>(p_x1, ln2_g, ln2_b, p_xn);
    gemm_tf32<EPI_BIAS | EPI_GELU><<<dim3(HIDDEN / GBN, MB), 256, GEMM_SMEM>>>(
        p_xn, w_fc1, b_fc1, nullptr, p_h, TOK, HIDDEN, DIM);
    gemm_tf32<EPI_BIAS | EPI_RES><<<dim3(DIM / GBN, MB), 256, GEMM_SMEM>>>(
        p_h, w_fc2, b_fc2, p_x1, out, TOK, DIM, HIDDEN);
}

// round 7
// speedup vs baseline: 2.8890x; 1.2542x over previous
#include <cuda_runtime.h>
#include <cuda_bf16.h>
#include <math.h>

// ---------------------------------------------------------------------------
// Problem constants
// ---------------------------------------------------------------------------
#define BATCH   16
#define SEQ     577
#define TOK     (BATCH * SEQ)        // 9232
#define DIM     1024
#define HEADS   16
#define HDIM    64
#define HIDDEN  4096
#define EPS     1e-5f
#define SCALE   0.125f

// ---------------------------------------------------------------------------
// Scratch
// ---------------------------------------------------------------------------
__device__ float g_xn [TOK * DIM];
__device__ float g_qkv[TOK * 3 * DIM];
__device__ float g_y  [TOK * DIM];
__device__ float g_x1 [TOK * DIM];
__device__ float g_h  [TOK * HIDDEN];

// ---------------------------------------------------------------------------
// Common helpers
// ---------------------------------------------------------------------------
__device__ __forceinline__ unsigned f2tf32(float f) {
    unsigned u;
    asm("cvt.rna.tf32.f32 %0, %1;" : "=r"(u) : "f"(f));
    return u;
}
__device__ __forceinline__ float tf32r(float f) {
    return __uint_as_float(f2tf32(f));
}
__device__ __forceinline__ void mma_tf32(
    float c[4], unsigned a0, unsigned a1, unsigned a2, unsigned a3,
    unsigned b0, unsigned b1)
{
    asm volatile(
        "mma.sync.aligned.m16n8k8.row.col.f32.tf32.tf32.f32 "
        "{%0,%1,%2,%3}, {%4,%5,%6,%7}, {%8,%9}, {%0,%1,%2,%3};\n"
        : "+f"(c[0]), "+f"(c[1]), "+f"(c[2]), "+f"(c[3])
        : "r"(a0), "r"(a1), "r"(a2), "r"(a3), "r"(b0), "r"(b1));
}
__device__ __forceinline__ void cp_async16(void* smem_dst, const void* gsrc) {
    unsigned s = (unsigned)__cvta_generic_to_shared(smem_dst);
    asm volatile("cp.async.cg.shared.global [%0], [%1], 16;\n" :: "r"(s), "l"(gsrc));
}
__device__ __forceinline__ void cp_commit() {
    asm volatile("cp.async.commit_group;\n");
}
template<int N>
__device__ __forceinline__ void cp_wait() {
    asm volatile("cp.async.wait_group %0;\n" :: "n"(N));
}

// ---------------------------------------------------------------------------
// LayerNorm
// ---------------------------------------------------------------------------
__device__ __forceinline__ float block_reduce_sum(float v, float* red) {
    int lane = threadIdx.x & 31, wid = threadIdx.x >> 5;
    #pragma unroll
    for (int o = 16; o > 0; o >>= 1) v += __shfl_xor_sync(0xffffffffu, v, o);
    if (lane == 0) red[wid] = v;
    __syncthreads();
    v = (lane < 8) ? red[lane] : 0.f;
    #pragma unroll
    for (int o = 4; o > 0; o >>= 1) v += __shfl_xor_sync(0xffffffffu, v, o);
    v = __shfl_sync(0xffffffffu, v, 0);
    return v;
}

__global__ __launch_bounds__(256) void ln_kernel(
    const float* __restrict__ x, const float* __restrict__ g,
    const float* __restrict__ b, float* __restrict__ out)
{
    __shared__ float red[8];
    size_t row = blockIdx.x;
    const float4* xr = (const float4*)(x + row * DIM);
    int t = threadIdx.x;
    float4 v = xr[t];
    float s = v.x + v.y + v.z + v.w;
    float mean = block_reduce_sum(s, red) * (1.f / DIM);
    __syncthreads();
    float dx0 = v.x - mean, dx1 = v.y - mean, dx2 = v.z - mean, dx3 = v.w - mean;
    float s2 = dx0*dx0 + dx1*dx1 + dx2*dx2 + dx3*dx3;
    float var = block_reduce_sum(s2, red) * (1.f / DIM);
    float rs = rsqrtf(var + EPS);
    float4 gg = ((const float4*)g)[t];
    float4 bb = ((const float4*)b)[t];
    float4 o;
    o.x = dx0 * rs * gg.x + bb.x;
    o.y = dx1 * rs * gg.y + bb.y;
    o.z = dx2 * rs * gg.z + bb.z;
    o.w = dx3 * rs * gg.w + bb.w;
    ((float4*)(out + row * DIM))[t] = o;
}

// ---------------------------------------------------------------------------
// TF32 GEMM-NT: 256x128x16 CTA, cp.async double buffer
// ---------------------------------------------------------------------------
#define EPI_BIAS 1
#define EPI_GELU 2
#define EPI_RES  4

#define GBM 256
#define GBN 128
#define GBK 16
#define RST 20
#define A_FLOATS (GBM * RST)
#define B_FLOATS (GBN * RST)
#define GEMM_SMEM ((2 * A_FLOATS + 2 * B_FLOATS) * (int)sizeof(float))

template<int FLAGS>
__global__ __launch_bounds__(256, 1) void gemm_tf32(
    const float* __restrict__ A, const float* __restrict__ Bw,
    const float* __restrict__ bias, const float* __restrict__ res,
    float* __restrict__ C, int M, int Nc, int K)
{
    extern __shared__ float sm[];
    float* Abuf[2] = { sm, sm + A_FLOATS };
    float* Bbuf[2] = { sm + 2 * A_FLOATS, sm + 2 * A_FLOATS + B_FLOATS };

    int tid = threadIdx.x;
    int m0 = blockIdx.y * GBM, n0 = blockIdx.x * GBN;

    int warp = tid >> 5, lane = tid & 31;
    int wm = warp & 3, wn = warp >> 2;
    int mb = wm * 64, nb = wn * 64;
    int g  = lane >> 2;
    int tg = lane & 3;

    int l_row = tid >> 2;
    int l_chk = (tid & 3) << 2;

    float acc[4][8][4];
    #pragma unroll
    for (int i = 0; i < 4; i++)
        #pragma unroll
        for (int j = 0; j < 8; j++)
            #pragma unroll
            for (int c = 0; c < 4; c++) acc[i][j][c] = 0.f;

    const int T = K / GBK;

    int arow[4];
    #pragma unroll
    for (int r = 0; r < 4; r++) {
        int rr = m0 + l_row + 64 * r;
        arow[r] = rr < M ? rr : M - 1;
    }

    {
        #pragma unroll
        for (int r = 0; r < 4; r++)
            cp_async16(&Abuf[0][(l_row + 64 * r) * RST + l_chk],
                       A + (size_t)arow[r] * K + l_chk);
        #pragma unroll
        for (int r = 0; r < 2; r++)
            cp_async16(&Bbuf[0][(l_row + 64 * r) * RST + l_chk],
                       Bw + (size_t)(n0 + l_row + 64 * r) * K + l_chk);
        cp_commit();
    }

    for (int t = 0; t < T; t++) {
        int buf = t & 1;
        if (t + 1 < T) {
            int k0 = (t + 1) * GBK;
            int nb2 = buf ^ 1;
            #pragma unroll
            for (int r = 0; r < 4; r++)
                cp_async16(&Abuf[nb2][(l_row + 64 * r) * RST + l_chk],
                           A + (size_t)arow[r] * K + k0 + l_chk);
            #pragma unroll
            for (int r = 0; r < 2; r++)
                cp_async16(&Bbuf[nb2][(l_row + 64 * r) * RST + l_chk],
                           Bw + (size_t)(n0 + l_row + 64 * r) * K + k0 + l_chk);
            cp_commit();
            cp_wait<1>();
        } else {
            cp_wait<0>();
        }
        __syncthreads();

        const float* as = Abuf[buf];
        const float* bs = Bbuf[buf];
        #pragma unroll
        for (int ks = 0; ks < 2; ks++) {
            int kk = ks * 8;
            unsigned a[4][4];
            #pragma unroll
            for (int i = 0; i < 4; i++) {
                int r0 = (mb + i * 16 + g) * RST + kk + tg;
                a[i][0] = f2tf32(as[r0]);
                a[i][1] = f2tf32(as[r0 + 8 * RST]);
                a[i][2] = f2tf32(as[r0 + 4]);
                a[i][3] = f2tf32(as[r0 + 8 * RST + 4]);
            }
            #pragma unroll
            for (int j = 0; j < 8; j++) {
                int c0 = (nb + j * 8 + g) * RST + kk + tg;
                unsigned b0 = f2tf32(bs[c0]);
                unsigned b1 = f2tf32(bs[c0 + 4]);
                #pragma unroll
                for (int i = 0; i < 4; i++)
                    mma_tf32(acc[i][j], a[i][0], a[i][1], a[i][2], a[i][3], b0, b1);
            }
        }
        __syncthreads();
    }

    #pragma unroll
    for (int i = 0; i < 4; i++) {
        #pragma unroll
        for (int j = 0; j < 8; j++) {
            int row0 = m0 + mb + i * 16 + g;
            int col  = n0 + nb + j * 8 + tg * 2;
            float bia0 = 0.f, bia1 = 0.f;
            if (FLAGS & EPI_BIAS) { bia0 = bias[col]; bia1 = bias[col + 1]; }
            #pragma unroll
            for (int half = 0; half < 2; half++) {
                int r = row0 + half * 8;
                if (r < M) {
                    float v0 = acc[i][j][half * 2 + 0] + bia0;
                    float v1 = acc[i][j][half * 2 + 1] + bia1;
                    if (FLAGS & EPI_GELU) {
                        v0 = 0.5f * v0 * (1.f + erff(v0 * 0.70710678118654752f));
                        v1 = 0.5f * v1 * (1.f + erff(v1 * 0.70710678118654752f));
                    }
                    size_t base = (size_t)r * Nc + col;
                    if (FLAGS & EPI_RES) {
                        float2 rr = *(const float2*)(res + base);
                        v0 += rr.x; v1 += rr.y;
                    }
                    float2 o; o.x = v0; o.y = v1;
                    *(float2*)(C + base) = o;
                }
            }
        }
    }
}

// ---------------------------------------------------------------------------
// Attention v3.2: flash-style online softmax.
// R6 bug fixed: K/V loaders now cover the FULL 64x64 tile (64 rows x 16
// float4 chunks), not just the first 16 floats of each row.
// ---------------------------------------------------------------------------
#define FQ    64
#define FC    64
#define NCH   10
#define QST2  68
#define KST2  68
#define VST2  72
#define SST2  68
#define A_Q   0
#define A_S   (A_Q + FQ * QST2)
#define A_K   (A_S + FQ * SST2)
#define A_V   (A_K + 2 * FC * KST2)
#define A_M   (A_V + 2 * FC * VST2)
#define A_L   (A_M + FQ)
#define A_AL  (A_L + FQ)
#define ATT3_SMEM ((A_AL + FQ) * (int)sizeof(float))   // ~107KB

__global__ __launch_bounds__(256, 2) void attn3_kernel(
    const float* __restrict__ qkv, float* __restrict__ out)
{
    extern __shared__ float sm[];
    float* qs  = sm + A_Q;
    float* sc  = sm + A_S;
    float* kb0 = sm + A_K;
    float* vb0 = sm + A_V;
    float* m_s = sm + A_M;
    float* l_s = sm + A_L;
    float* a_s = sm + A_AL;

    int bh = blockIdx.y;
    int b = bh >> 4, h = bh & 15;
    int q0 = blockIdx.x * FQ;
    int t = threadIdx.x;
    int warp = t >> 5, lane = t & 31;
    int g = lane >> 2, tg = lane & 3;
    int mb = (warp & 3) * 16;
    int nb = (warp >> 2) * 32;

    const float* kq = qkv + (size_t)b * SEQ * (3 * DIM) + DIM + h * HDIM;
    const float* vq = qkv + (size_t)b * SEQ * (3 * DIM) + 2 * DIM + h * HDIM;

    // ---- load Q (tf32-rounded) + init stats ----
    for (int idx = t; idx < FQ * 16; idx += 256) {
        int r = idx >> 4, c4 = (idx & 15) << 2;
        int qr = q0 + r; if (qr >= SEQ) qr = SEQ - 1;
        float4 v = *(const float4*)(qkv + (size_t)(b * SEQ + qr) * (3 * DIM) + h * HDIM + c4);
        qs[r * QST2 + c4 + 0] = tf32r(v.x);
        qs[r * QST2 + c4 + 1] = tf32r(v.y);
        qs[r * QST2 + c4 + 2] = tf32r(v.z);
        qs[r * QST2 + c4 + 3] = tf32r(v.w);
    }
    if (t < FQ) { m_s[t] = -1e30f; l_s[t] = 0.f; }

    float oacc[4][4];
    #pragma unroll
    for (int j = 0; j < 4; j++)
        #pragma unroll
        for (int c = 0; c < 4; c++) oacc[j][c] = 0.f;

    // ---- prologue: chunk 0 K/V (full 64x64 tile: 16 float4 chunks per row) ----
    #pragma unroll
    for (int idx = t; idx < FC * 16; idx += 256) {
        int r = idx >> 4, c4 = (idx & 15) << 2;
        int kr = r; if (kr >= SEQ) kr = SEQ - 1;
        cp_async16(&kb0[r * KST2 + c4], kq + (size_t)kr * (3 * DIM) + c4);
        cp_async16(&vb0[r * VST2 + c4], vq + (size_t)kr * (3 * DIM) + c4);
    }
    cp_commit();

    for (int c = 0; c < NCH; c++) {
        int buf = c & 1;
        float* kbuf = kb0 + buf * FC * KST2;
        float* vbuf = vb0 + buf * FC * VST2;
        if (c + 1 < NCH) {
            float* kn = kb0 + (buf ^ 1) * FC * KST2;
            float* vn = vb0 + (buf ^ 1) * FC * VST2;
            #pragma unroll
            for (int idx = t; idx < FC * 16; idx += 256) {
                int r = idx >> 4, c4 = (idx & 15) << 2;
                int kr = (c + 1) * FC + r; if (kr >= SEQ) kr = SEQ - 1;
                cp_async16(&kn[r * KST2 + c4], kq + (size_t)kr * (3 * DIM) + c4);
                cp_async16(&vn[r * VST2 + c4], vq + (size_t)kr * (3 * DIM) + c4);
            }
            cp_commit();
            cp_wait<1>();
        } else {
            cp_wait<0>();
        }
        __syncthreads();

        // ---- S = Q @ K^T ----
        float sacc[4][4];
        #pragma unroll
        for (int j = 0; j < 4; j++)
            #pragma unroll
            for (int cc = 0; cc < 4; cc++) sacc[j][cc] = 0.f;

        #pragma unroll
        for (int k8 = 0; k8 < 8; k8++) {
            int kk = k8 * 8;
            unsigned a0 = __float_as_uint(qs[(mb + g) * QST2 + kk + tg]);
            unsigned a1 = __float_as_uint(qs[(mb + 8 + g) * QST2 + kk + tg]);
            unsigned a2 = __float_as_uint(qs[(mb + g) * QST2 + kk + tg + 4]);
            unsigned a3 = __float_as_uint(qs[(mb + 8 + g) * QST2 + kk + tg + 4]);
            #pragma unroll
            for (int j = 0; j < 4; j++) {
                unsigned b0 = f2tf32(kbuf[(nb + 8 * j + g) * KST2 + kk + tg]);
                unsigned b1 = f2tf32(kbuf[(nb + 8 * j + g) * KST2 + kk + tg + 4]);
                mma_tf32(sacc[j], a0, a1, a2, a3, b0, b1);
            }
        }

        // store S chunk with scale + column mask
        #pragma unroll
        for (int j = 0; j < 4; j++) {
            int col = nb + 8 * j + 2 * tg;
            int gcol = c * FC + col;
            int r0 = mb + g, r1 = r0 + 8;
            sc[r0 * SST2 + col]     = (gcol     < SEQ) ? sacc[j][0] * SCALE : -1e30f;
            sc[r0 * SST2 + col + 1] = (gcol + 1 < SEQ) ? sacc[j][1] * SCALE : -1e30f;
            sc[r1 * SST2 + col]     = (gcol     < SEQ) ? sacc[j][2] * SCALE : -1e30f;
            sc[r1 * SST2 + col + 1] = (gcol + 1 < SEQ) ? sacc[j][3] * SCALE : -1e30f;
        }
        __syncthreads();

        // ---- online softmax on chunk (4 threads/row) ----
        {
            int r = t >> 2, l = t & 3;
            float* row = sc + r * SST2;
            float cm = -1e30f;
            #pragma unroll
            for (int j = 0; j < 16; j++) cm = fmaxf(cm, row[l + 4 * j]);
            cm = fmaxf(cm, __shfl_xor_sync(0xffffffffu, cm, 1, 4));
            cm = fmaxf(cm, __shfl_xor_sync(0xffffffffu, cm, 2, 4));
            float mold = m_s[r];
            float mnew = fmaxf(mold, cm);
            float alpha = __expf(mold - mnew);
            float s = 0.f;
            #pragma unroll
            for (int j = 0; j < 16; j++) {
                float e = __expf(row[l + 4 * j] - mnew);
                row[l + 4 * j] = tf32r(e);
                s += e;
            }
            s += __shfl_xor_sync(0xffffffffu, s, 1, 4);
            s += __shfl_xor_sync(0xffffffffu, s, 2, 4);
            if (l == 0) {
                l_s[r] = l_s[r] * alpha + s;
                m_s[r] = mnew;
                a_s[r] = alpha;
            }
        }
        __syncthreads();

        // ---- rescale O, then O += P @ V ----
        {
            float al0 = a_s[mb + g], al1 = a_s[mb + 8 + g];
            #pragma unroll
            for (int j = 0; j < 4; j++) {
                oacc[j][0] *= al0; oacc[j][1] *= al0;
                oacc[j][2] *= al1; oacc[j][3] *= al1;
            }
        }
        #pragma unroll
        for (int k8 = 0; k8 < 8; k8++) {
            int kk = k8 * 8;
            unsigned a0 = __float_as_uint(sc[(mb + g) * SST2 + kk + tg]);
            unsigned a1 = __float_as_uint(sc[(mb + 8 + g) * SST2 + kk + tg]);
            unsigned a2 = __float_as_uint(sc[(mb + g) * SST2 + kk + tg + 4]);
            unsigned a3 = __float_as_uint(sc[(mb + 8 + g) * SST2 + kk + tg + 4]);
            #pragma unroll
            for (int j = 0; j < 4; j++) {
                unsigned b0 = f2tf32(vbuf[(kk + tg) * VST2 + nb + 8 * j + g]);
                unsigned b1 = f2tf32(vbuf[(kk + tg + 4) * VST2 + nb + 8 * j + g]);
                mma_tf32(oacc[j], a0, a1, a2, a3, b0, b1);
            }
        }
        // Close the WAR race: next iteration's prefetch overwrites the K/V
        // buffers this iteration's MMAs just read.
        __syncthreads();
    }

    // ---- epilogue: divide by l, store ----
    {
        float linv0 = 1.f / l_s[mb + g];
        float linv1 = 1.f / l_s[mb + 8 + g];
        #pragma unroll
        for (int j = 0; j < 4; j++) {
            int col = h * HDIM + nb + 8 * j + 2 * tg;
            int r0 = q0 + mb + g, r1 = r0 + 8;
            if (r0 < SEQ) {
                float2 o; o.x = oacc[j][0] * linv0; o.y = oacc[j][1] * linv0;
                *(float2*)(out + (size_t)(b * SEQ + r0) * DIM + col) = o;
            }
            if (r1 < SEQ) {
                float2 o; o.x = oacc[j][2] * linv1; o.y = oacc[j][3] * linv1;
                *(float2*)(out + (size_t)(b * SEQ + r1) * DIM + col) = o;
            }
        }
    }
}

// ---------------------------------------------------------------------------
// Launch
// ---------------------------------------------------------------------------
extern "C" void kernel_launch(void* const* d_in, const int* in_sizes, int n_in,
                              void* d_out, int out_size)
{
    const float* x      = (const float*)d_in[0];
    const float* w_qkv  = (const float*)d_in[1];
    const float* b_qkv  = (const float*)d_in[2];
    const float* w_proj = (const float*)d_in[3];
    const float* b_proj = (const float*)d_in[4];
    const float* ln1_g  = (const float*)d_in[5];
    const float* ln1_b  = (const float*)d_in[6];
    const float* ln2_g  = (const float*)d_in[7];
    const float* ln2_b  = (const float*)d_in[8];
    const float* w_fc1  = (const float*)d_in[9];
    const float* b_fc1  = (const float*)d_in[10];
    const float* w_fc2  = (const float*)d_in[11];
    const float* b_fc2  = (const float*)d_in[12];
    float* out = (float*)d_out;

    float *p_xn, *p_qkv, *p_y, *p_x1, *p_h;
    cudaGetSymbolAddress((void**)&p_xn,  g_xn);
    cudaGetSymbolAddress((void**)&p_qkv, g_qkv);
    cudaGetSymbolAddress((void**)&p_y,   g_y);
    cudaGetSymbolAddress((void**)&p_x1,  g_x1);
    cudaGetSymbolAddress((void**)&p_h,   g_h);

    cudaFuncSetAttribute(attn3_kernel,
        cudaFuncAttributeMaxDynamicSharedMemorySize, ATT3_SMEM);
    cudaFuncSetAttribute(gemm_tf32<EPI_BIAS>,
        cudaFuncAttributeMaxDynamicSharedMemorySize, GEMM_SMEM);
    cudaFuncSetAttribute(gemm_tf32<EPI_BIAS | EPI_RES>,
        cudaFuncAttributeMaxDynamicSharedMemorySize, GEMM_SMEM);
    cudaFuncSetAttribute(gemm_tf32<EPI_BIAS | EPI_GELU>,
        cudaFuncAttributeMaxDynamicSharedMemorySize, GEMM_SMEM);

    const int MB = (TOK + GBM - 1) / GBM;   // 37

    ln_kernel<<<TOK, 256>>>(x, ln1_g, ln1_b, p_xn);
    gemm_tf32<EPI_BIAS><<<dim3(3 * DIM / GBN, MB), 256, GEMM_SMEM>>>(
        p_xn, w_qkv, b_qkv, nullptr, p_qkv, TOK, 3 * DIM, DIM);
    attn3_kernel<<<dim3((SEQ + FQ - 1) / FQ, BATCH * HEADS), 256, ATT3_SMEM>>>(
        p_qkv, p_y);
    gemm_tf32<EPI_BIAS | EPI_RES><<<dim3(DIM / GBN, MB), 256, GEMM_SMEM>>>(
        p_y, w_proj, b_proj, x, p_x1, TOK, DIM, DIM);
    ln_kernel<<<TOK, 256>>>(p_x1, ln2_g, ln2_b, p_xn);
    gemm_tf32<EPI_BIAS | EPI_GELU><<<dim3(HIDDEN / GBN, MB), 256, GEMM_SMEM>>>(
        p_xn, w_fc1, b_fc1, nullptr, p_h, TOK, HIDDEN, DIM);
    gemm_tf32<EPI_BIAS | EPI_RES><<<dim3(DIM / GBN, MB), 256, GEMM_SMEM>>>(
        p_h, w_fc2, b_fc2, p_x1, out, TOK, DIM, HIDDEN);
}

// round 8
// speedup vs baseline: 2.9816x; 1.0321x over previous
#include <cuda_runtime.h>
#include <cuda_bf16.h>
#include <math.h>

// ---------------------------------------------------------------------------
// Problem constants
// ---------------------------------------------------------------------------
#define BATCH   16
#define SEQ     577
#define TOK     (BATCH * SEQ)        // 9232
#define DIM     1024
#define HEADS   16
#define HDIM    64
#define HIDDEN  4096
#define EPS     1e-5f
#define SCALE   0.125f

// ---------------------------------------------------------------------------
// Scratch
// ---------------------------------------------------------------------------
__device__ float g_xn [TOK * DIM];
__device__ float g_qkv[TOK * 3 * DIM];
__device__ float g_y  [TOK * DIM];
__device__ float g_x1 [TOK * DIM];
__device__ float g_h  [TOK * HIDDEN];

// ---------------------------------------------------------------------------
// Common helpers
// ---------------------------------------------------------------------------
__device__ __forceinline__ unsigned f2tf32(float f) {
    unsigned u;
    asm("cvt.rna.tf32.f32 %0, %1;" : "=r"(u) : "f"(f));
    return u;
}
__device__ __forceinline__ float tf32r(float f) {
    return __uint_as_float(f2tf32(f));
}
__device__ __forceinline__ void mma_tf32(
    float c[4], unsigned a0, unsigned a1, unsigned a2, unsigned a3,
    unsigned b0, unsigned b1)
{
    asm volatile(
        "mma.sync.aligned.m16n8k8.row.col.f32.tf32.tf32.f32 "
        "{%0,%1,%2,%3}, {%4,%5,%6,%7}, {%8,%9}, {%0,%1,%2,%3};\n"
        : "+f"(c[0]), "+f"(c[1]), "+f"(c[2]), "+f"(c[3])
        : "r"(a0), "r"(a1), "r"(a2), "r"(a3), "r"(b0), "r"(b1));
}
__device__ __forceinline__ void cp_async16(void* smem_dst, const void* gsrc) {
    unsigned s = (unsigned)__cvta_generic_to_shared(smem_dst);
    asm volatile("cp.async.cg.shared.global [%0], [%1], 16;\n" :: "r"(s), "l"(gsrc));
}
__device__ __forceinline__ void cp_commit() {
    asm volatile("cp.async.commit_group;\n");
}
template<int N>
__device__ __forceinline__ void cp_wait() {
    asm volatile("cp.async.wait_group %0;\n" :: "n"(N));
}

// ---------------------------------------------------------------------------
// LayerNorm
// ---------------------------------------------------------------------------
__device__ __forceinline__ float block_reduce_sum(float v, float* red) {
    int lane = threadIdx.x & 31, wid = threadIdx.x >> 5;
    #pragma unroll
    for (int o = 16; o > 0; o >>= 1) v += __shfl_xor_sync(0xffffffffu, v, o);
    if (lane == 0) red[wid] = v;
    __syncthreads();
    v = (lane < 8) ? red[lane] : 0.f;
    #pragma unroll
    for (int o = 4; o > 0; o >>= 1) v += __shfl_xor_sync(0xffffffffu, v, o);
    v = __shfl_sync(0xffffffffu, v, 0);
    return v;
}

__global__ __launch_bounds__(256) void ln_kernel(
    const float* __restrict__ x, const float* __restrict__ g,
    const float* __restrict__ b, float* __restrict__ out)
{
    __shared__ float red[8];
    size_t row = blockIdx.x;
    const float4* xr = (const float4*)(x + row * DIM);
    int t = threadIdx.x;
    float4 v = xr[t];
    float s = v.x + v.y + v.z + v.w;
    float mean = block_reduce_sum(s, red) * (1.f / DIM);
    __syncthreads();
    float dx0 = v.x - mean, dx1 = v.y - mean, dx2 = v.z - mean, dx3 = v.w - mean;
    float s2 = dx0*dx0 + dx1*dx1 + dx2*dx2 + dx3*dx3;
    float var = block_reduce_sum(s2, red) * (1.f / DIM);
    float rs = rsqrtf(var + EPS);
    float4 gg = ((const float4*)g)[t];
    float4 bb = ((const float4*)b)[t];
    float4 o;
    o.x = dx0 * rs * gg.x + bb.x;
    o.y = dx1 * rs * gg.y + bb.y;
    o.z = dx2 * rs * gg.z + bb.z;
    o.w = dx3 * rs * gg.w + bb.w;
    ((float4*)(out + row * DIM))[t] = o;
}

// ---------------------------------------------------------------------------
// TF32 GEMM-NT v3: 256x128x16 CTA, 512 threads (16 warps, warp tile 64x32),
// cp.async double buffer. Doubled warp occupancy vs v2 (~64 acc regs/thread).
// ---------------------------------------------------------------------------
#define EPI_BIAS 1
#define EPI_GELU 2
#define EPI_RES  4

#define GBM 256
#define GBN 128
#define GBK 16
#define RST 20
#define A_FLOATS (GBM * RST)
#define B_FLOATS (GBN * RST)
#define GEMM_SMEM ((2 * A_FLOATS + 2 * B_FLOATS) * (int)sizeof(float))

template<int FLAGS>
__global__ __launch_bounds__(512, 1) void gemm_tf32(
    const float* __restrict__ A, const float* __restrict__ Bw,
    const float* __restrict__ bias, const float* __restrict__ res,
    float* __restrict__ C, int M, int Nc, int K)
{
    extern __shared__ float sm[];
    float* Abuf[2] = { sm, sm + A_FLOATS };
    float* Bbuf[2] = { sm + 2 * A_FLOATS, sm + 2 * A_FLOATS + B_FLOATS };

    int tid = threadIdx.x;
    int m0 = blockIdx.y * GBM, n0 = blockIdx.x * GBN;

    int warp = tid >> 5, lane = tid & 31;
    int wm = warp & 3, wn = warp >> 2;      // 4 m x 4 n warp grid
    int mb = wm * 64, nb = wn * 32;
    int g  = lane >> 2;
    int tg = lane & 3;

    int l_row = tid >> 2;                   // 0..127
    int l_chk = (tid & 3) << 2;

    float acc[4][4][4];
    #pragma unroll
    for (int i = 0; i < 4; i++)
        #pragma unroll
        for (int j = 0; j < 4; j++)
            #pragma unroll
            for (int c = 0; c < 4; c++) acc[i][j][c] = 0.f;

    const int T = K / GBK;

    int arow[2];
    #pragma unroll
    for (int r = 0; r < 2; r++) {
        int rr = m0 + l_row + 128 * r;
        arow[r] = rr < M ? rr : M - 1;
    }

    {
        #pragma unroll
        for (int r = 0; r < 2; r++)
            cp_async16(&Abuf[0][(l_row + 128 * r) * RST + l_chk],
                       A + (size_t)arow[r] * K + l_chk);
        cp_async16(&Bbuf[0][l_row * RST + l_chk],
                   Bw + (size_t)(n0 + l_row) * K + l_chk);
        cp_commit();
    }

    for (int t = 0; t < T; t++) {
        int buf = t & 1;
        if (t + 1 < T) {
            int k0 = (t + 1) * GBK;
            int nb2 = buf ^ 1;
            #pragma unroll
            for (int r = 0; r < 2; r++)
                cp_async16(&Abuf[nb2][(l_row + 128 * r) * RST + l_chk],
                           A + (size_t)arow[r] * K + k0 + l_chk);
            cp_async16(&Bbuf[nb2][l_row * RST + l_chk],
                       Bw + (size_t)(n0 + l_row) * K + k0 + l_chk);
            cp_commit();
            cp_wait<1>();
        } else {
            cp_wait<0>();
        }
        __syncthreads();

        const float* as = Abuf[buf];
        const float* bs = Bbuf[buf];
        #pragma unroll
        for (int ks = 0; ks < 2; ks++) {
            int kk = ks * 8;
            unsigned a[4][4];
            #pragma unroll
            for (int i = 0; i < 4; i++) {
                int r0 = (mb + i * 16 + g) * RST + kk + tg;
                a[i][0] = f2tf32(as[r0]);
                a[i][1] = f2tf32(as[r0 + 8 * RST]);
                a[i][2] = f2tf32(as[r0 + 4]);
                a[i][3] = f2tf32(as[r0 + 8 * RST + 4]);
            }
            #pragma unroll
            for (int j = 0; j < 4; j++) {
                int c0 = (nb + j * 8 + g) * RST + kk + tg;
                unsigned b0 = f2tf32(bs[c0]);
                unsigned b1 = f2tf32(bs[c0 + 4]);
                #pragma unroll
                for (int i = 0; i < 4; i++)
                    mma_tf32(acc[i][j], a[i][0], a[i][1], a[i][2], a[i][3], b0, b1);
            }
        }
        __syncthreads();
    }

    #pragma unroll
    for (int i = 0; i < 4; i++) {
        #pragma unroll
        for (int j = 0; j < 4; j++) {
            int row0 = m0 + mb + i * 16 + g;
            int col  = n0 + nb + j * 8 + tg * 2;
            float bia0 = 0.f, bia1 = 0.f;
            if (FLAGS & EPI_BIAS) { bia0 = bias[col]; bia1 = bias[col + 1]; }
            #pragma unroll
            for (int half = 0; half < 2; half++) {
                int r = row0 + half * 8;
                if (r < M) {
                    float v0 = acc[i][j][half * 2 + 0] + bia0;
                    float v1 = acc[i][j][half * 2 + 1] + bia1;
                    if (FLAGS & EPI_GELU) {
                        v0 = 0.5f * v0 * (1.f + erff(v0 * 0.70710678118654752f));
                        v1 = 0.5f * v1 * (1.f + erff(v1 * 0.70710678118654752f));
                    }
                    size_t base = (size_t)r * Nc + col;
                    if (FLAGS & EPI_RES) {
                        float2 rr = *(const float2*)(res + base);
                        v0 += rr.x; v1 += rr.y;
                    }
                    float2 o; o.x = v0; o.y = v1;
                    *(float2*)(C + base) = o;
                }
            }
        }
    }
}

// ---------------------------------------------------------------------------
// Attention v4: register-resident flash attention.
// 128 queries/CTA (8 warps x 16 rows; each warp spans all 64 key cols).
// S/P never touch smem: softmax + online stats in registers (shfl over the
// 4-lane groups); P reshaped to mma A-fragments via intra-warp shuffles.
// 2 barriers per chunk. Smem ~104KB -> 2 CTAs/SM.
// ---------------------------------------------------------------------------
#define FQ4   128
#define FC4   64
#define NCH4  10
#define QST4  68
#define KST4  68
#define VST4  72
#define A4_Q  0
#define A4_K  (A4_Q + FQ4 * QST4)               // 8704
#define A4_V  (A4_K + 2 * FC4 * KST4)           // 17408
#define ATT4_SMEM ((A4_V + 2 * FC4 * VST4) * (int)sizeof(float))  // 106496

__global__ __launch_bounds__(256, 2) void attn4_kernel(
    const float* __restrict__ qkv, float* __restrict__ out)
{
    extern __shared__ float sm[];
    float* qs = sm + A4_Q;
    float* kb = sm + A4_K;
    float* vb = sm + A4_V;

    int bh = blockIdx.y;
    int b = bh >> 4, h = bh & 15;
    int q0 = blockIdx.x * FQ4;
    int t = threadIdx.x;
    int warp = t >> 5, lane = t & 31;
    int g = lane >> 2, tg = lane & 3;
    int mb = warp * 16;

    const float* kq = qkv + (size_t)b * SEQ * (3 * DIM) + DIM + h * HDIM;
    const float* vq = qkv + (size_t)b * SEQ * (3 * DIM) + 2 * DIM + h * HDIM;

    // ---- load Q (tf32-rounded) ----
    for (int idx = t; idx < FQ4 * 16; idx += 256) {
        int r = idx >> 4, c4 = (idx & 15) << 2;
        int qr = q0 + r; if (qr >= SEQ) qr = SEQ - 1;
        float4 v = *(const float4*)(qkv + (size_t)(b * SEQ + qr) * (3 * DIM) + h * HDIM + c4);
        qs[r * QST4 + c4 + 0] = tf32r(v.x);
        qs[r * QST4 + c4 + 1] = tf32r(v.y);
        qs[r * QST4 + c4 + 2] = tf32r(v.z);
        qs[r * QST4 + c4 + 3] = tf32r(v.w);
    }

    float m0 = -1e30f, m1 = -1e30f, l0 = 0.f, l1 = 0.f;
    float oacc[8][4];
    #pragma unroll
    for (int j = 0; j < 8; j++)
        #pragma unroll
        for (int c = 0; c < 4; c++) oacc[j][c] = 0.f;

    // ---- prologue: chunk 0 K/V ----
    for (int idx = t; idx < FC4 * 16; idx += 256) {
        int r = idx >> 4, c4 = (idx & 15) << 2;
        int kr = r; if (kr >= SEQ) kr = SEQ - 1;
        cp_async16(&kb[r * KST4 + c4], kq + (size_t)kr * (3 * DIM) + c4);
        cp_async16(&vb[r * VST4 + c4], vq + (size_t)kr * (3 * DIM) + c4);
    }
    cp_commit();

    for (int c = 0; c < NCH4; c++) {
        int buf = c & 1;
        const float* kbuf = kb + buf * FC4 * KST4;
        const float* vbuf = vb + buf * FC4 * VST4;
        if (c + 1 < NCH4) {
            float* kn = kb + (buf ^ 1) * FC4 * KST4;
            float* vn = vb + (buf ^ 1) * FC4 * VST4;
            for (int idx = t; idx < FC4 * 16; idx += 256) {
                int r = idx >> 4, c4 = (idx & 15) << 2;
                int kr = (c + 1) * FC4 + r; if (kr >= SEQ) kr = SEQ - 1;
                cp_async16(&kn[r * KST4 + c4], kq + (size_t)kr * (3 * DIM) + c4);
                cp_async16(&vn[r * VST4 + c4], vq + (size_t)kr * (3 * DIM) + c4);
            }
            cp_commit();
            cp_wait<1>();
        } else {
            cp_wait<0>();
        }
        __syncthreads();

        // ---- S = Q @ K^T  (warp: 16 rows x 64 keys, in registers) ----
        float p[8][4];
        #pragma unroll
        for (int j = 0; j < 8; j++)
            #pragma unroll
            for (int e = 0; e < 4; e++) p[j][e] = 0.f;

        #pragma unroll
        for (int k8 = 0; k8 < 8; k8++) {
            int kk = k8 * 8;
            unsigned a0 = __float_as_uint(qs[(mb + g) * QST4 + kk + tg]);
            unsigned a1 = __float_as_uint(qs[(mb + 8 + g) * QST4 + kk + tg]);
            unsigned a2 = __float_as_uint(qs[(mb + g) * QST4 + kk + tg + 4]);
            unsigned a3 = __float_as_uint(qs[(mb + 8 + g) * QST4 + kk + tg + 4]);
            #pragma unroll
            for (int j = 0; j < 8; j++) {
                unsigned b0 = f2tf32(kbuf[(8 * j + g) * KST4 + kk + tg]);
                unsigned b1 = f2tf32(kbuf[(8 * j + g) * KST4 + kk + tg + 4]);
                mma_tf32(p[j], a0, a1, a2, a3, b0, b1);
            }
        }

        // ---- scale + key-column mask (register) ----
        #pragma unroll
        for (int j = 0; j < 8; j++) {
            int gcol = c * FC4 + 8 * j + 2 * tg;
            bool ok0 = (gcol < SEQ), ok1 = (gcol + 1 < SEQ);
            p[j][0] = ok0 ? p[j][0] * SCALE : -1e30f;
            p[j][1] = ok1 ? p[j][1] * SCALE : -1e30f;
            p[j][2] = ok0 ? p[j][2] * SCALE : -1e30f;
            p[j][3] = ok1 ? p[j][3] * SCALE : -1e30f;
        }

        // ---- online softmax in registers (rows g and g+8) ----
        float cm0 = -1e30f, cm1 = -1e30f;
        #pragma unroll
        for (int j = 0; j < 8; j++) {
            cm0 = fmaxf(cm0, fmaxf(p[j][0], p[j][1]));
            cm1 = fmaxf(cm1, fmaxf(p[j][2], p[j][3]));
        }
        cm0 = fmaxf(cm0, __shfl_xor_sync(0xffffffffu, cm0, 1, 4));
        cm0 = fmaxf(cm0, __shfl_xor_sync(0xffffffffu, cm0, 2, 4));
        cm1 = fmaxf(cm1, __shfl_xor_sync(0xffffffffu, cm1, 1, 4));
        cm1 = fmaxf(cm1, __shfl_xor_sync(0xffffffffu, cm1, 2, 4));

        float mn0 = fmaxf(m0, cm0), mn1 = fmaxf(m1, cm1);
        float al0 = __expf(m0 - mn0), al1 = __expf(m1 - mn1);
        float s0 = 0.f, s1 = 0.f;
        #pragma unroll
        for (int j = 0; j < 8; j++) {
            p[j][0] = __expf(p[j][0] - mn0); s0 += p[j][0];
            p[j][1] = __expf(p[j][1] - mn0); s0 += p[j][1];
            p[j][2] = __expf(p[j][2] - mn1); s1 += p[j][2];
            p[j][3] = __expf(p[j][3] - mn1); s1 += p[j][3];
        }
        s0 += __shfl_xor_sync(0xffffffffu, s0, 1, 4);
        s0 += __shfl_xor_sync(0xffffffffu, s0, 2, 4);
        s1 += __shfl_xor_sync(0xffffffffu, s1, 1, 4);
        s1 += __shfl_xor_sync(0xffffffffu, s1, 2, 4);
        l0 = l0 * al0 + s0;  m0 = mn0;
        l1 = l1 * al1 + s1;  m1 = mn1;

        // ---- rescale O ----
        #pragma unroll
        for (int j = 0; j < 8; j++) {
            oacc[j][0] *= al0; oacc[j][1] *= al0;
            oacc[j][2] *= al1; oacc[j][3] *= al1;
        }

        // ---- O += P @ V  (P from registers via intra-warp shuffle) ----
        int srcA = (lane & ~3) | (tg >> 1);
        int srcB = srcA + 2;
        #pragma unroll
        for (int jj = 0; jj < 8; jj++) {
            // A-fragment: a0=P[g][8jj+tg], a1=P[g+8][8jj+tg],
            //             a2=P[g][8jj+tg+4], a3=P[g+8][8jj+tg+4]
            float s00 = __shfl_sync(0xffffffffu, p[jj][0], srcA);
            float s01 = __shfl_sync(0xffffffffu, p[jj][1], srcA);
            float s10 = __shfl_sync(0xffffffffu, p[jj][2], srcA);
            float s11 = __shfl_sync(0xffffffffu, p[jj][3], srcA);
            float s20 = __shfl_sync(0xffffffffu, p[jj][0], srcB);
            float s21 = __shfl_sync(0xffffffffu, p[jj][1], srcB);
            float s30 = __shfl_sync(0xffffffffu, p[jj][2], srcB);
            float s31 = __shfl_sync(0xffffffffu, p[jj][3], srcB);
            bool odd = (tg & 1);
            unsigned A0 = f2tf32(odd ? s01 : s00);
            unsigned A1 = f2tf32(odd ? s11 : s10);
            unsigned A2 = f2tf32(odd ? s21 : s20);
            unsigned A3 = f2tf32(odd ? s31 : s30);
            #pragma unroll
            for (int j2 = 0; j2 < 8; j2++) {
                unsigned b0 = f2tf32(vbuf[(8 * jj + tg) * VST4 + 8 * j2 + g]);
                unsigned b1 = f2tf32(vbuf[(8 * jj + tg + 4) * VST4 + 8 * j2 + g]);
                mma_tf32(oacc[j2], A0, A1, A2, A3, b0, b1);
            }
        }
        // WAR barrier: next iteration's prefetch overwrites this K/V buffer.
        __syncthreads();
    }

    // ---- epilogue ----
    {
        float li0 = 1.f / l0, li1 = 1.f / l1;
        #pragma unroll
        for (int j2 = 0; j2 < 8; j2++) {
            int col = h * HDIM + 8 * j2 + 2 * tg;
            int r0 = q0 + mb + g, r1 = r0 + 8;
            if (r0 < SEQ) {
                float2 o; o.x = oacc[j2][0] * li0; o.y = oacc[j2][1] * li0;
                *(float2*)(out + (size_t)(b * SEQ + r0) * DIM + col) = o;
            }
            if (r1 < SEQ) {
                float2 o; o.x = oacc[j2][2] * li1; o.y = oacc[j2][3] * li1;
                *(float2*)(out + (size_t)(b * SEQ + r1) * DIM + col) = o;
            }
        }
    }
}

// ---------------------------------------------------------------------------
// Launch
// ---------------------------------------------------------------------------
extern "C" void kernel_launch(void* const* d_in, const int* in_sizes, int n_in,
                              void* d_out, int out_size)
{
    const float* x      = (const float*)d_in[0];
    const float* w_qkv  = (const float*)d_in[1];
    const float* b_qkv  = (const float*)d_in[2];
    const float* w_proj = (const float*)d_in[3];
    const float* b_proj = (const float*)d_in[4];
    const float* ln1_g  = (const float*)d_in[5];
    const float* ln1_b  = (const float*)d_in[6];
    const float* ln2_g  = (const float*)d_in[7];
    const float* ln2_b  = (const float*)d_in[8];
    const float* w_fc1  = (const float*)d_in[9];
    const float* b_fc1  = (const float*)d_in[10];
    const float* w_fc2  = (const float*)d_in[11];
    const float* b_fc2  = (const float*)d_in[12];
    float* out = (float*)d_out;

    float *p_xn, *p_qkv, *p_y, *p_x1, *p_h;
    cudaGetSymbolAddress((void**)&p_xn,  g_xn);
    cudaGetSymbolAddress((void**)&p_qkv, g_qkv);
    cudaGetSymbolAddress((void**)&p_y,   g_y);
    cudaGetSymbolAddress((void**)&p_x1,  g_x1);
    cudaGetSymbolAddress((void**)&p_h,   g_h);

    cudaFuncSetAttribute(attn4_kernel,
        cudaFuncAttributeMaxDynamicSharedMemorySize, ATT4_SMEM);
    cudaFuncSetAttribute(gemm_tf32<EPI_BIAS>,
        cudaFuncAttributeMaxDynamicSharedMemorySize, GEMM_SMEM);
    cudaFuncSetAttribute(gemm_tf32<EPI_BIAS | EPI_RES>,
        cudaFuncAttributeMaxDynamicSharedMemorySize, GEMM_SMEM);
    cudaFuncSetAttribute(gemm_tf32<EPI_BIAS | EPI_GELU>,
        cudaFuncAttributeMaxDynamicSharedMemorySize, GEMM_SMEM);

    const int MB = (TOK + GBM - 1) / GBM;   // 37

    ln_kernel<<<TOK, 256>>>(x, ln1_g, ln1_b, p_xn);
    gemm_tf32<EPI_BIAS><<<dim3(3 * DIM / GBN, MB), 512, GEMM_SMEM>>>(
        p_xn, w_qkv, b_qkv, nullptr, p_qkv, TOK, 3 * DIM, DIM);
    attn4_kernel<<<dim3((SEQ + FQ4 - 1) / FQ4, BATCH * HEADS), 256, ATT4_SMEM>>>(
        p_qkv, p_y);
    gemm_tf32<EPI_BIAS | EPI_RES><<<dim3(DIM / GBN, MB), 512, GEMM_SMEM>>>(
        p_y, w_proj, b_proj, x, p_x1, TOK, DIM, DIM);
    ln_kernel<<<TOK, 256>>>(p_x1, ln2_g, ln2_b, p_xn);
    gemm_tf32<EPI_BIAS | EPI_GELU><<<dim3(HIDDEN / GBN, MB), 512, GEMM_SMEM>>>(
        p_xn, w_fc1, b_fc1, nullptr, p_h, TOK, HIDDEN, DIM);
    gemm_tf32<EPI_BIAS | EPI_RES><<<dim3(DIM / GBN, MB), 512, GEMM_SMEM>>>(
        p_h, w_fc2, b_fc2, p_x1, out, TOK, DIM, HIDDEN);
}

// round 9
// speedup vs baseline: 3.1121x; 1.0438x over previous
#include <cuda_runtime.h>
#include <cuda_bf16.h>
#include <math.h>

// ---------------------------------------------------------------------------
// Problem constants
// ---------------------------------------------------------------------------
#define BATCH   16
#define SEQ     577
#define TOK     (BATCH * SEQ)        // 9232
#define DIM     1024
#define HEADS   16
#define HDIM    64
#define HIDDEN  4096
#define EPS     1e-5f
#define SCALE   0.125f
#define SCL2    0.18033688011112042f   // SCALE * log2(e)

// ---------------------------------------------------------------------------
// Scratch
// ---------------------------------------------------------------------------
__device__ float g_xn [TOK * DIM];
__device__ float g_qkv[TOK * 3 * DIM];
__device__ float g_y  [TOK * DIM];
__device__ float g_x1 [TOK * DIM];
__device__ float g_h  [TOK * HIDDEN];
// tf32-pre-rounded weights
__device__ float g_wq [3 * DIM * DIM];
__device__ float g_wp [DIM * DIM];
__device__ float g_w1 [HIDDEN * DIM];
__device__ float g_w2 [DIM * HIDDEN];

// ---------------------------------------------------------------------------
// Common helpers
// ---------------------------------------------------------------------------
__device__ __forceinline__ unsigned f2tf32(float f) {
    unsigned u;
    asm("cvt.rna.tf32.f32 %0, %1;" : "=r"(u) : "f"(f));
    return u;
}
__device__ __forceinline__ float tf32r(float f) {
    return __uint_as_float(f2tf32(f));
}
__device__ __forceinline__ void mma_tf32(
    float c[4], unsigned a0, unsigned a1, unsigned a2, unsigned a3,
    unsigned b0, unsigned b1)
{
    asm volatile(
        "mma.sync.aligned.m16n8k8.row.col.f32.tf32.tf32.f32 "
        "{%0,%1,%2,%3}, {%4,%5,%6,%7}, {%8,%9}, {%0,%1,%2,%3};\n"
        : "+f"(c[0]), "+f"(c[1]), "+f"(c[2]), "+f"(c[3])
        : "r"(a0), "r"(a1), "r"(a2), "r"(a3), "r"(b0), "r"(b1));
}
__device__ __forceinline__ void cp_async16(void* smem_dst, const void* gsrc) {
    unsigned s = (unsigned)__cvta_generic_to_shared(smem_dst);
    asm volatile("cp.async.cg.shared.global [%0], [%1], 16;\n" :: "r"(s), "l"(gsrc));
}
__device__ __forceinline__ void cp_commit() {
    asm volatile("cp.async.commit_group;\n");
}
template<int N>
__device__ __forceinline__ void cp_wait() {
    asm volatile("cp.async.wait_group %0;\n" :: "n"(N));
}

// Fast 2^x on the FMA/ALU pipes (no MUFU). Valid x <= ~60; clamps at -126.
// Degree-6 Taylor of 2^f, rel err ~2e-5.
__device__ __forceinline__ float exp2_fast(float x) {
    float xc = fmaxf(x, -126.f);
    float fi = floorf(xc);
    float f = xc - fi;
    float p = 1.5403530e-4f;
    p = fmaf(p, f, 1.3333558e-3f);
    p = fmaf(p, f, 9.6181291e-3f);
    p = fmaf(p, f, 5.5504109e-2f);
    p = fmaf(p, f, 2.4022651e-1f);
    p = fmaf(p, f, 6.9314718e-1f);
    p = fmaf(p, f, 1.0f);
    int i = (int)fi;
    return __int_as_float((i + 127) << 23) * p;
}

// ---------------------------------------------------------------------------
// tf32 pre-round kernel (weights)
// ---------------------------------------------------------------------------
__global__ __launch_bounds__(256) void tf32_round_kernel(
    const float* __restrict__ in, float* __restrict__ out, int n4)
{
    int i = blockIdx.x * 256 + threadIdx.x;
    if (i < n4) {
        float4 v = ((const float4*)in)[i];
        float4 o;
        o.x = tf32r(v.x); o.y = tf32r(v.y); o.z = tf32r(v.z); o.w = tf32r(v.w);
        ((float4*)out)[i] = o;
    }
}

// ---------------------------------------------------------------------------
// LayerNorm (output tf32-rounded: it is only consumed as a GEMM A operand)
// ---------------------------------------------------------------------------
__device__ __forceinline__ float block_reduce_sum(float v, float* red) {
    int lane = threadIdx.x & 31, wid = threadIdx.x >> 5;
    #pragma unroll
    for (int o = 16; o > 0; o >>= 1) v += __shfl_xor_sync(0xffffffffu, v, o);
    if (lane == 0) red[wid] = v;
    __syncthreads();
    v = (lane < 8) ? red[lane] : 0.f;
    #pragma unroll
    for (int o = 4; o > 0; o >>= 1) v += __shfl_xor_sync(0xffffffffu, v, o);
    v = __shfl_sync(0xffffffffu, v, 0);
    return v;
}

__global__ __launch_bounds__(256) void ln_kernel(
    const float* __restrict__ x, const float* __restrict__ g,
    const float* __restrict__ b, float* __restrict__ out)
{
    __shared__ float red[8];
    size_t row = blockIdx.x;
    const float4* xr = (const float4*)(x + row * DIM);
    int t = threadIdx.x;
    float4 v = xr[t];
    float s = v.x + v.y + v.z + v.w;
    float mean = block_reduce_sum(s, red) * (1.f / DIM);
    __syncthreads();
    float dx0 = v.x - mean, dx1 = v.y - mean, dx2 = v.z - mean, dx3 = v.w - mean;
    float s2 = dx0*dx0 + dx1*dx1 + dx2*dx2 + dx3*dx3;
    float var = block_reduce_sum(s2, red) * (1.f / DIM);
    float rs = rsqrtf(var + EPS);
    float4 gg = ((const float4*)g)[t];
    float4 bb = ((const float4*)b)[t];
    float4 o;
    o.x = tf32r(dx0 * rs * gg.x + bb.x);
    o.y = tf32r(dx1 * rs * gg.y + bb.y);
    o.z = tf32r(dx2 * rs * gg.z + bb.z);
    o.w = tf32r(dx3 * rs * gg.w + bb.w);
    ((float4*)(out + row * DIM))[t] = o;
}

// ---------------------------------------------------------------------------
// TF32 GEMM-NT: 256x128x16 CTA, 512 threads. Operands are PRE-ROUNDED tf32
// in memory -> fragment loads are raw bit loads (no cvt in the mainloop).
// ---------------------------------------------------------------------------
#define EPI_BIAS 1
#define EPI_GELU 2
#define EPI_RES  4
#define EPI_T32O 8    // round output to tf32 (next consumer uses it as mma operand)

#define GBM 256
#define GBN 128
#define GBK 16
#define RST 20
#define A_FLOATS (GBM * RST)
#define B_FLOATS (GBN * RST)
#define GEMM_SMEM ((2 * A_FLOATS + 2 * B_FLOATS) * (int)sizeof(float))

template<int FLAGS>
__global__ __launch_bounds__(512, 1) void gemm_tf32(
    const float* __restrict__ A, const float* __restrict__ Bw,
    const float* __restrict__ bias, const float* __restrict__ res,
    float* __restrict__ C, int M, int Nc, int K)
{
    extern __shared__ float sm[];
    float* Abuf[2] = { sm, sm + A_FLOATS };
    float* Bbuf[2] = { sm + 2 * A_FLOATS, sm + 2 * A_FLOATS + B_FLOATS };

    int tid = threadIdx.x;
    int m0 = blockIdx.y * GBM, n0 = blockIdx.x * GBN;

    int warp = tid >> 5, lane = tid & 31;
    int wm = warp & 3, wn = warp >> 2;      // 4 m x 4 n warp grid
    int mb = wm * 64, nb = wn * 32;
    int g  = lane >> 2;
    int tg = lane & 3;

    int l_row = tid >> 2;                   // 0..127
    int l_chk = (tid & 3) << 2;

    float acc[4][4][4];
    #pragma unroll
    for (int i = 0; i < 4; i++)
        #pragma unroll
        for (int j = 0; j < 4; j++)
            #pragma unroll
            for (int c = 0; c < 4; c++) acc[i][j][c] = 0.f;

    const int T = K / GBK;

    int arow[2];
    #pragma unroll
    for (int r = 0; r < 2; r++) {
        int rr = m0 + l_row + 128 * r;
        arow[r] = rr < M ? rr : M - 1;
    }

    {
        #pragma unroll
        for (int r = 0; r < 2; r++)
            cp_async16(&Abuf[0][(l_row + 128 * r) * RST + l_chk],
                       A + (size_t)arow[r] * K + l_chk);
        cp_async16(&Bbuf[0][l_row * RST + l_chk],
                   Bw + (size_t)(n0 + l_row) * K + l_chk);
        cp_commit();
    }

    for (int t = 0; t < T; t++) {
        int buf = t & 1;
        if (t + 1 < T) {
            int k0 = (t + 1) * GBK;
            int nb2 = buf ^ 1;
            #pragma unroll
            for (int r = 0; r < 2; r++)
                cp_async16(&Abuf[nb2][(l_row + 128 * r) * RST + l_chk],
                           A + (size_t)arow[r] * K + k0 + l_chk);
            cp_async16(&Bbuf[nb2][l_row * RST + l_chk],
                       Bw + (size_t)(n0 + l_row) * K + k0 + l_chk);
            cp_commit();
            cp_wait<1>();
        } else {
            cp_wait<0>();
        }
        __syncthreads();

        const unsigned* as = (const unsigned*)Abuf[buf];
        const unsigned* bs = (const unsigned*)Bbuf[buf];
        #pragma unroll
        for (int ks = 0; ks < 2; ks++) {
            int kk = ks * 8;
            unsigned a[4][4];
            #pragma unroll
            for (int i = 0; i < 4; i++) {
                int r0 = (mb + i * 16 + g) * RST + kk + tg;
                a[i][0] = as[r0];
                a[i][1] = as[r0 + 8 * RST];
                a[i][2] = as[r0 + 4];
                a[i][3] = as[r0 + 8 * RST + 4];
            }
            #pragma unroll
            for (int j = 0; j < 4; j++) {
                int c0 = (nb + j * 8 + g) * RST + kk + tg;
                unsigned b0 = bs[c0];
                unsigned b1 = bs[c0 + 4];
                #pragma unroll
                for (int i = 0; i < 4; i++)
                    mma_tf32(acc[i][j], a[i][0], a[i][1], a[i][2], a[i][3], b0, b1);
            }
        }
        __syncthreads();
    }

    #pragma unroll
    for (int i = 0; i < 4; i++) {
        #pragma unroll
        for (int j = 0; j < 4; j++) {
            int row0 = m0 + mb + i * 16 + g;
            int col  = n0 + nb + j * 8 + tg * 2;
            float bia0 = 0.f, bia1 = 0.f;
            if (FLAGS & EPI_BIAS) { bia0 = bias[col]; bia1 = bias[col + 1]; }
            #pragma unroll
            for (int half = 0; half < 2; half++) {
                int r = row0 + half * 8;
                if (r < M) {
                    float v0 = acc[i][j][half * 2 + 0] + bia0;
                    float v1 = acc[i][j][half * 2 + 1] + bia1;
                    if (FLAGS & EPI_GELU) {
                        v0 = 0.5f * v0 * (1.f + erff(v0 * 0.70710678118654752f));
                        v1 = 0.5f * v1 * (1.f + erff(v1 * 0.70710678118654752f));
                    }
                    size_t base = (size_t)r * Nc + col;
                    if (FLAGS & EPI_RES) {
                        float2 rr = *(const float2*)(res + base);
                        v0 += rr.x; v1 += rr.y;
                    }
                    if (FLAGS & EPI_T32O) { v0 = tf32r(v0); v1 = tf32r(v1); }
                    float2 o; o.x = v0; o.y = v1;
                    *(float2*)(C + base) = o;
                }
            }
        }
    }
}

// ---------------------------------------------------------------------------
// Attention v5: register flash attention; qkv is pre-rounded tf32 so all
// operand loads are raw bits; softmax uses FMA-pipe exp2 (base-2 domain).
// ---------------------------------------------------------------------------
#define FQ4   128
#define FC4   64
#define NCH4  10
#define QST4  68
#define KST4  68
#define VST4  72
#define A4_Q  0
#define A4_K  (A4_Q + FQ4 * QST4)               // 8704
#define A4_V  (A4_K + 2 * FC4 * KST4)           // 17408
#define ATT4_SMEM ((A4_V + 2 * FC4 * VST4) * (int)sizeof(float))  // 106496

__global__ __launch_bounds__(256, 2) void attn5_kernel(
    const float* __restrict__ qkv, float* __restrict__ out)
{
    extern __shared__ float sm[];
    float* qs = sm + A4_Q;
    float* kb = sm + A4_K;
    float* vb = sm + A4_V;

    int bh = blockIdx.y;
    int b = bh >> 4, h = bh & 15;
    int q0 = blockIdx.x * FQ4;
    int t = threadIdx.x;
    int warp = t >> 5, lane = t & 31;
    int g = lane >> 2, tg = lane & 3;
    int mb = warp * 16;

    const float* kq = qkv + (size_t)b * SEQ * (3 * DIM) + DIM + h * HDIM;
    const float* vq = qkv + (size_t)b * SEQ * (3 * DIM) + 2 * DIM + h * HDIM;

    // ---- load Q (already tf32-rounded by the qkv GEMM epilogue) ----
    for (int idx = t; idx < FQ4 * 16; idx += 256) {
        int r = idx >> 4, c4 = (idx & 15) << 2;
        int qr = q0 + r; if (qr >= SEQ) qr = SEQ - 1;
        float4 v = *(const float4*)(qkv + (size_t)(b * SEQ + qr) * (3 * DIM) + h * HDIM + c4);
        *(float4*)(qs + r * QST4 + c4) = v;
    }

    float m0 = -1e30f, m1 = -1e30f, l0 = 0.f, l1 = 0.f;
    float oacc[8][4];
    #pragma unroll
    for (int j = 0; j < 8; j++)
        #pragma unroll
        for (int c = 0; c < 4; c++) oacc[j][c] = 0.f;

    // ---- prologue: chunk 0 K/V ----
    for (int idx = t; idx < FC4 * 16; idx += 256) {
        int r = idx >> 4, c4 = (idx & 15) << 2;
        int kr = r; if (kr >= SEQ) kr = SEQ - 1;
        cp_async16(&kb[r * KST4 + c4], kq + (size_t)kr * (3 * DIM) + c4);
        cp_async16(&vb[r * VST4 + c4], vq + (size_t)kr * (3 * DIM) + c4);
    }
    cp_commit();

    for (int c = 0; c < NCH4; c++) {
        int buf = c & 1;
        const float* kbuf = kb + buf * FC4 * KST4;
        const float* vbuf = vb + buf * FC4 * VST4;
        if (c + 1 < NCH4) {
            float* kn = kb + (buf ^ 1) * FC4 * KST4;
            float* vn = vb + (buf ^ 1) * FC4 * VST4;
            for (int idx = t; idx < FC4 * 16; idx += 256) {
                int r = idx >> 4, c4 = (idx & 15) << 2;
                int kr = (c + 1) * FC4 + r; if (kr >= SEQ) kr = SEQ - 1;
                cp_async16(&kn[r * KST4 + c4], kq + (size_t)kr * (3 * DIM) + c4);
                cp_async16(&vn[r * VST4 + c4], vq + (size_t)kr * (3 * DIM) + c4);
            }
            cp_commit();
            cp_wait<1>();
        } else {
            cp_wait<0>();
        }
        __syncthreads();

        // ---- S = Q @ K^T  (raw bit fragment loads) ----
        float p[8][4];
        #pragma unroll
        for (int j = 0; j < 8; j++)
            #pragma unroll
            for (int e = 0; e < 4; e++) p[j][e] = 0.f;

        const unsigned* ku = (const unsigned*)kbuf;
        const unsigned* qu = (const unsigned*)qs;
        #pragma unroll
        for (int k8 = 0; k8 < 8; k8++) {
            int kk = k8 * 8;
            unsigned a0 = qu[(mb + g) * QST4 + kk + tg];
            unsigned a1 = qu[(mb + 8 + g) * QST4 + kk + tg];
            unsigned a2 = qu[(mb + g) * QST4 + kk + tg + 4];
            unsigned a3 = qu[(mb + 8 + g) * QST4 + kk + tg + 4];
            #pragma unroll
            for (int j = 0; j < 8; j++) {
                unsigned b0 = ku[(8 * j + g) * KST4 + kk + tg];
                unsigned b1 = ku[(8 * j + g) * KST4 + kk + tg + 4];
                mma_tf32(p[j], a0, a1, a2, a3, b0, b1);
            }
        }

        // ---- scale into base-2 domain + key-column mask ----
        #pragma unroll
        for (int j = 0; j < 8; j++) {
            int gcol = c * FC4 + 8 * j + 2 * tg;
            bool ok0 = (gcol < SEQ), ok1 = (gcol + 1 < SEQ);
            p[j][0] = ok0 ? p[j][0] * SCL2 : -1e30f;
            p[j][1] = ok1 ? p[j][1] * SCL2 : -1e30f;
            p[j][2] = ok0 ? p[j][2] * SCL2 : -1e30f;
            p[j][3] = ok1 ? p[j][3] * SCL2 : -1e30f;
        }

        // ---- online softmax (base-2, FMA-pipe exp2) ----
        float cm0 = -1e30f, cm1 = -1e30f;
        #pragma unroll
        for (int j = 0; j < 8; j++) {
            cm0 = fmaxf(cm0, fmaxf(p[j][0], p[j][1]));
            cm1 = fmaxf(cm1, fmaxf(p[j][2], p[j][3]));
        }
        cm0 = fmaxf(cm0, __shfl_xor_sync(0xffffffffu, cm0, 1, 4));
        cm0 = fmaxf(cm0, __shfl_xor_sync(0xffffffffu, cm0, 2, 4));
        cm1 = fmaxf(cm1, __shfl_xor_sync(0xffffffffu, cm1, 1, 4));
        cm1 = fmaxf(cm1, __shfl_xor_sync(0xffffffffu, cm1, 2, 4));

        float mn0 = fmaxf(m0, cm0), mn1 = fmaxf(m1, cm1);
        float al0 = exp2_fast(m0 - mn0), al1 = exp2_fast(m1 - mn1);
        float s0 = 0.f, s1 = 0.f;
        #pragma unroll
        for (int j = 0; j < 8; j++) {
            p[j][0] = exp2_fast(p[j][0] - mn0); s0 += p[j][0];
            p[j][1] = exp2_fast(p[j][1] - mn0); s0 += p[j][1];
            p[j][2] = exp2_fast(p[j][2] - mn1); s1 += p[j][2];
            p[j][3] = exp2_fast(p[j][3] - mn1); s1 += p[j][3];
        }
        s0 += __shfl_xor_sync(0xffffffffu, s0, 1, 4);
        s0 += __shfl_xor_sync(0xffffffffu, s0, 2, 4);
        s1 += __shfl_xor_sync(0xffffffffu, s1, 1, 4);
        s1 += __shfl_xor_sync(0xffffffffu, s1, 2, 4);
        l0 = l0 * al0 + s0;  m0 = mn0;
        l1 = l1 * al1 + s1;  m1 = mn1;

        // ---- rescale O ----
        #pragma unroll
        for (int j = 0; j < 8; j++) {
            oacc[j][0] *= al0; oacc[j][1] *= al0;
            oacc[j][2] *= al1; oacc[j][3] *= al1;
        }

        // ---- O += P @ V  (P via intra-warp shuffle; V raw bits) ----
        const unsigned* vu = (const unsigned*)vbuf;
        int srcA = (lane & ~3) | (tg >> 1);
        int srcB = srcA + 2;
        #pragma unroll
        for (int jj = 0; jj < 8; jj++) {
            float s00 = __shfl_sync(0xffffffffu, p[jj][0], srcA);
            float s01 = __shfl_sync(0xffffffffu, p[jj][1], srcA);
            float s10 = __shfl_sync(0xffffffffu, p[jj][2], srcA);
            float s11 = __shfl_sync(0xffffffffu, p[jj][3], srcA);
            float s20 = __shfl_sync(0xffffffffu, p[jj][0], srcB);
            float s21 = __shfl_sync(0xffffffffu, p[jj][1], srcB);
            float s30 = __shfl_sync(0xffffffffu, p[jj][2], srcB);
            float s31 = __shfl_sync(0xffffffffu, p[jj][3], srcB);
            bool odd = (tg & 1);
            unsigned A0 = f2tf32(odd ? s01 : s00);
            unsigned A1 = f2tf32(odd ? s11 : s10);
            unsigned A2 = f2tf32(odd ? s21 : s20);
            unsigned A3 = f2tf32(odd ? s31 : s30);
            #pragma unroll
            for (int j2 = 0; j2 < 8; j2++) {
                unsigned b0 = vu[(8 * jj + tg) * VST4 + 8 * j2 + g];
                unsigned b1 = vu[(8 * jj + tg + 4) * VST4 + 8 * j2 + g];
                mma_tf32(oacc[j2], A0, A1, A2, A3, b0, b1);
            }
        }
        // WAR barrier: next iteration's prefetch overwrites this K/V buffer.
        __syncthreads();
    }

    // ---- epilogue: divide by l, round to tf32 (proj consumes as A), store ----
    {
        float li0 = 1.f / l0, li1 = 1.f / l1;
        #pragma unroll
        for (int j2 = 0; j2 < 8; j2++) {
            int col = h * HDIM + 8 * j2 + 2 * tg;
            int r0 = q0 + mb + g, r1 = r0 + 8;
            if (r0 < SEQ) {
                float2 o; o.x = tf32r(oacc[j2][0] * li0); o.y = tf32r(oacc[j2][1] * li0);
                *(float2*)(out + (size_t)(b * SEQ + r0) * DIM + col) = o;
            }
            if (r1 < SEQ) {
                float2 o; o.x = tf32r(oacc[j2][2] * li1); o.y = tf32r(oacc[j2][3] * li1);
                *(float2*)(out + (size_t)(b * SEQ + r1) * DIM + col) = o;
            }
        }
    }
}

// ---------------------------------------------------------------------------
// Launch
// ---------------------------------------------------------------------------
extern "C" void kernel_launch(void* const* d_in, const int* in_sizes, int n_in,
                              void* d_out, int out_size)
{
    const float* x      = (const float*)d_in[0];
    const float* w_qkv  = (const float*)d_in[1];
    const float* b_qkv  = (const float*)d_in[2];
    const float* w_proj = (const float*)d_in[3];
    const float* b_proj = (const float*)d_in[4];
    const float* ln1_g  = (const float*)d_in[5];
    const float* ln1_b  = (const float*)d_in[6];
    const float* ln2_g  = (const float*)d_in[7];
    const float* ln2_b  = (const float*)d_in[8];
    const float* w_fc1  = (const float*)d_in[9];
    const float* b_fc1  = (const float*)d_in[10];
    const float* w_fc2  = (const float*)d_in[11];
    const float* b_fc2  = (const float*)d_in[12];
    float* out = (float*)d_out;

    float *p_xn, *p_qkv, *p_y, *p_x1, *p_h, *p_wq, *p_wp, *p_w1, *p_w2;
    cudaGetSymbolAddress((void**)&p_xn,  g_xn);
    cudaGetSymbolAddress((void**)&p_qkv, g_qkv);
    cudaGetSymbolAddress((void**)&p_y,   g_y);
    cudaGetSymbolAddress((void**)&p_x1,  g_x1);
    cudaGetSymbolAddress((void**)&p_h,   g_h);
    cudaGetSymbolAddress((void**)&p_wq,  g_wq);
    cudaGetSymbolAddress((void**)&p_wp,  g_wp);
    cudaGetSymbolAddress((void**)&p_w1,  g_w1);
    cudaGetSymbolAddress((void**)&p_w2,  g_w2);

    cudaFuncSetAttribute(attn5_kernel,
        cudaFuncAttributeMaxDynamicSharedMemorySize, ATT4_SMEM);
    cudaFuncSetAttribute(gemm_tf32<EPI_BIAS | EPI_T32O>,
        cudaFuncAttributeMaxDynamicSharedMemorySize, GEMM_SMEM);
    cudaFuncSetAttribute(gemm_tf32<EPI_BIAS | EPI_RES>,
        cudaFuncAttributeMaxDynamicSharedMemorySize, GEMM_SMEM);
    cudaFuncSetAttribute(gemm_tf32<EPI_BIAS | EPI_GELU | EPI_T32O>,
        cudaFuncAttributeMaxDynamicSharedMemorySize, GEMM_SMEM);

    const int MB = (TOK + GBM - 1) / GBM;   // 37

    // pre-round weights to tf32 (cheap: ~50MB r+w)
    tf32_round_kernel<<<(3 * DIM * DIM / 4 + 255) / 256, 256>>>(w_qkv, p_wq, 3 * DIM * DIM / 4);
    tf32_round_kernel<<<(DIM * DIM / 4 + 255) / 256, 256>>>(w_proj, p_wp, DIM * DIM / 4);
    tf32_round_kernel<<<(HIDDEN * DIM / 4 + 255) / 256, 256>>>(w_fc1, p_w1, HIDDEN * DIM / 4);
    tf32_round_kernel<<<(DIM * HIDDEN / 4 + 255) / 256, 256>>>(w_fc2, p_w2, DIM * HIDDEN / 4);

    ln_kernel<<<TOK, 256>>>(x, ln1_g, ln1_b, p_xn);
    gemm_tf32<EPI_BIAS | EPI_T32O><<<dim3(3 * DIM / GBN, MB), 512, GEMM_SMEM>>>(
        p_xn, p_wq, b_qkv, nullptr, p_qkv, TOK, 3 * DIM, DIM);
    attn5_kernel<<<dim3((SEQ + FQ4 - 1) / FQ4, BATCH * HEADS), 256, ATT4_SMEM>>>(
        p_qkv, p_y);
    gemm_tf32<EPI_BIAS | EPI_RES><<<dim3(DIM / GBN, MB), 512, GEMM_SMEM>>>(
        p_y, p_wp, b_proj, x, p_x1, TOK, DIM, DIM);
    ln_kernel<<<TOK, 256>>>(p_x1, ln2_g, ln2_b, p_xn);
    gemm_tf32<EPI_BIAS | EPI_GELU | EPI_T32O><<<dim3(HIDDEN / GBN, MB), 512, GEMM_SMEM>>>(
        p_xn, p_w1, b_fc1, nullptr, p_h, TOK, HIDDEN, DIM);
    gemm_tf32<EPI_BIAS | EPI_RES><<<dim3(DIM / GBN, MB), 512, GEMM_SMEM>>>(
        p_h, p_w2, b_fc2, p_x1, out, TOK, DIM, HIDDEN);
}